// round 3
// baseline (speedup 1.0000x reference)
#include <cuda_runtime.h>
#include <math.h>
#include <stdint.h>

// ---------------------------------------------------------------------------
// Problem constants
// ---------------------------------------------------------------------------
#define BQ      8
#define LQ      128
#define NIMG    1024          // BQ * LQ
#define DQ      256           // VID_FEAT + N_MFCC
#define EDQ     512           // 2*DQ
#define NSTQ    16
#define DTRQ    16
#define NLQ     4
#define VID_FEAT 196
#define N_MFCC   60

// ---------------------------------------------------------------------------
// Scratch (device globals; allocation-free per harness rules)
// ---------------------------------------------------------------------------
__device__ float g_pool1[(size_t)NIMG * 32 * 32 * 32];   // conv1+pool out
__device__ float g_feat [NIMG * 64];                     // conv2+pool+mean out
__device__ float g_xc   [NIMG * DQ];                     // concat feats / fwd stream
__device__ float g_xz   [NIMG * 2 * EDQ];                // in_proj out (x | z)
__device__ float g_xcs  [NIMG * EDQ];                    // conv+silu out
__device__ float g_dbc  [NIMG * 48];                     // x_proj out (dt|B|C)
__device__ float g_ys   [NIMG * EDQ];                    // scan out (gated)
__device__ float g_xb   [BQ * DQ];                       // bwd mamba stream
__device__ float g_fill [32];                            // filler target

// ---------------------------------------------------------------------------
// tf32 mma helpers
// ---------------------------------------------------------------------------
__device__ __forceinline__ void mma_tf32(float* c, float a0, float a1,
                                         float a2, float a3,
                                         float b0, float b1) {
    asm volatile(
        "mma.sync.aligned.m16n8k8.row.col.f32.tf32.tf32.f32 "
        "{%0,%1,%2,%3}, {%4,%5,%6,%7}, {%8,%9}, {%0,%1,%2,%3};"
        : "+f"(c[0]), "+f"(c[1]), "+f"(c[2]), "+f"(c[3])
        : "r"(__float_as_uint(a0)), "r"(__float_as_uint(a1)),
          "r"(__float_as_uint(a2)), "r"(__float_as_uint(a3)),
          "r"(__float_as_uint(b0)), "r"(__float_as_uint(b1)));
}

__device__ __forceinline__ float to_tf32(float v) {
    uint32_t u;
    asm("cvt.rna.tf32.f32 %0, %1;" : "=r"(u) : "f"(v));
    return __uint_as_float(u);
}

// ---------------------------------------------------------------------------
// conv1 via tf32 mma implicit GEMM + bias + relu + maxpool2, pooled store
// per image: C[4096 pos, 32 oc] = im2col[4096, 27pad32] @ W[27, 32]
// smem: X[3][64][64] (12288 f), Ws[32][40] (zero-padded k>=27), sb[32]
// ---------------------------------------------------------------------------
#define C1_SMEM_FLOATS (12288 + 32 * 40 + 32)
#define C1_SMEM_BYTES  (C1_SMEM_FLOATS * 4)

__global__ void __launch_bounds__(256) k_conv1_mma(const float* __restrict__ video,
                                                   const float* __restrict__ w,
                                                   const float* __restrict__ bias) {
    extern __shared__ float sm[];
    float* Xs = sm;                  // 12288
    float* Ws = Xs + 12288;          // 32*40
    float* sb = Ws + 32 * 40;        // 32
    int n = blockIdx.x;
    int tid = threadIdx.x;

    const float* img = video + (size_t)n * 12288;
    for (int i = tid; i < 12288; i += 256) Xs[i] = to_tf32(img[i]);
    for (int i = tid; i < 1280;  i += 256) Ws[i] = 0.f;
    if (tid < 32) sb[tid] = bias[tid];
    __syncthreads();
    for (int i = tid; i < 864; i += 256) {
        int oc = i / 27, r = i % 27;          // r = ic*9 + ky*3 + kx = k
        Ws[r * 40 + oc] = to_tf32(w[i]);
    }
    __syncthreads();

    int lane = tid & 31, wp = tid >> 5;
    int g = lane >> 2, l4 = lane & 3;
    int xh = wp & 3, yp = wp >> 2;            // 4 x-segments, 2 y-pairs
    int x0 = xh * 16;

    // per-thread k-column lookup (columns l4 and l4+4 of each k-step)
    int ky0[4], kx0[4], ic0[4];
    int ky1[4], kx1[4], ic1[4];
#pragma unroll
    for (int kk = 0; kk < 4; ++kk) {
        int k0 = kk * 8 + l4;
        int k1 = k0 + 4;
        if (k0 < 27) { ic0[kk] = (k0 / 9) * 4096; int t = k0 % 9; ky0[kk] = t / 3; kx0[kk] = t % 3; }
        else         { ic0[kk] = 0; ky0[kk] = 1; kx0[kk] = 1; }
        if (k1 < 27) { ic1[kk] = (k1 / 9) * 4096; int t = k1 % 9; ky1[kk] = t / 3; kx1[kk] = t % 3; }
        else         { ic1[kk] = 0; ky1[kk] = 1; kx1[kk] = 1; }
    }

    for (int chunk = 0; chunk < 16; ++chunk) {
        int y = chunk * 4 + yp * 2;           // rows y, y+1 (pool pair)
        float acc[2][4][4];
#pragma unroll
        for (int t = 0; t < 2; ++t)
#pragma unroll
            for (int j = 0; j < 4; ++j)
#pragma unroll
                for (int i = 0; i < 4; ++i) acc[t][j][i] = 0.f;

#pragma unroll
        for (int kk = 0; kk < 4; ++kk) {
            int yA0 = y + ky0[kk] - 1,  yA1 = y + ky1[kk] - 1;
            int xgA = x0 + g + kx0[kk] - 1;
            int xgB = x0 + g + kx1[kk] - 1;
            bool pA0 = (unsigned)xgA < 64u, pA1 = (unsigned)(xgA + 8) < 64u;
            bool pB0 = (unsigned)xgB < 64u, pB1 = (unsigned)(xgB + 8) < 64u;
            bool y00 = (unsigned)yA0 < 64u, y01 = (unsigned)(yA0 + 1) < 64u;
            bool y10 = (unsigned)yA1 < 64u, y11 = (unsigned)(yA1 + 1) < 64u;
            const float* xb0 = Xs + ic0[kk] + yA0 * 64;
            const float* xb1 = Xs + ic1[kk] + yA1 * 64;
            float a0 = (y00 && pA0) ? xb0[xgA]          : 0.f;
            float a1 = (y00 && pA1) ? xb0[xgA + 8]      : 0.f;
            float a2 = (y10 && pB0) ? xb1[xgB]          : 0.f;
            float a3 = (y10 && pB1) ? xb1[xgB + 8]      : 0.f;
            float e0 = (y01 && pA0) ? xb0[64 + xgA]     : 0.f;
            float e1 = (y01 && pA1) ? xb0[64 + xgA + 8] : 0.f;
            float e2 = (y11 && pB0) ? xb1[64 + xgB]     : 0.f;
            float e3 = (y11 && pB1) ? xb1[64 + xgB + 8] : 0.f;
            const float* w0 = Ws + (kk * 8 + l4) * 40 + g;
            const float* w1 = w0 + 4 * 40;
#pragma unroll
            for (int j = 0; j < 4; ++j) {
                float b0 = w0[8 * j];
                float b1 = w1[8 * j];
                mma_tf32(acc[0][j], a0, a1, a2, a3, b0, b1);
                mma_tf32(acc[1][j], e0, e1, e2, e3, b0, b1);
            }
        }

        // bias + y-pool + x-pool(shfl 4) + relu + pooled store
        int py = chunk * 2 + yp;
#pragma unroll
        for (int j = 0; j < 4; ++j)
#pragma unroll
            for (int i = 0; i < 4; ++i) {
                float m = fmaxf(acc[0][j][i], acc[1][j][i]);
                m = fmaxf(m, __shfl_xor_sync(0xffffffffu, m, 4));
                int oc = 8 * j + 2 * l4 + (i & 1);
                m = fmaxf(m + sb[oc], 0.f);
                if ((g & 1) == 0) {
                    int px = ((x0 + g) >> 1) + ((i >= 2) ? 4 : 0);
                    g_pool1[(((size_t)n * 32 + oc) << 10) + (py << 5) + px] = m;
                }
            }
    }
}

// ---------------------------------------------------------------------------
// conv2 via tf32 mma implicit GEMM + relu + maxpool2 + mean  (verified R2)
// ---------------------------------------------------------------------------
#define XS_FLOATS (32 * 1032)
#define WS_FLOATS (288 * 72)
#define C2_SMEM_BYTES ((XS_FLOATS + WS_FLOATS + 64 + 512) * 4)

__global__ void __launch_bounds__(256) k_conv2_mma(const float* __restrict__ w,
                                                   const float* __restrict__ bias) {
    extern __shared__ float sm[];
    float* Xs  = sm;
    float* Ws  = Xs + XS_FLOATS;
    float* sb  = Ws + WS_FLOATS;
    float* red = sb + 64;
    int n = blockIdx.x;
    int tid = threadIdx.x;

    const float* src = g_pool1 + (size_t)n * 32768;
    for (int i = tid; i < 32768; i += 256) {
        int ic = i >> 10, s = i & 1023;
        Xs[ic * 1032 + s] = to_tf32(src[i]);
    }
    for (int i = tid; i < 18432; i += 256) {
        int oc = i / 288, r = i % 288;
        int ic = r / 9, kk = r % 9;
        Ws[(kk * 32 + ic) * 72 + oc] = to_tf32(w[i]);
    }
    if (tid < 64) sb[tid] = bias[tid];
    __syncthreads();

    int lane = tid & 31, wp = tid >> 5;
    int g = lane >> 2, l4 = lane & 3;
    int ypair = wp >> 1, xh = wp & 1;
    int x0 = xh * 16;

    float cs[8][2];
#pragma unroll
    for (int j = 0; j < 8; ++j) { cs[j][0] = 0.f; cs[j][1] = 0.f; }

    for (int c = 0; c < 4; ++c) {
        int y = c * 8 + ypair * 2;
        float acc[2][8][4];
#pragma unroll
        for (int t = 0; t < 2; ++t)
#pragma unroll
            for (int j = 0; j < 8; ++j)
#pragma unroll
                for (int i = 0; i < 4; ++i) acc[t][j][i] = 0.f;

#pragma unroll
        for (int ky = 0; ky < 3; ++ky) {
            int yA = y + ky - 1;
            int yB = yA + 1;
            bool yokA = (unsigned)yA < 32u;
            bool yokB = (unsigned)yB < 32u;
#pragma unroll
            for (int kx = 0; kx < 3; ++kx) {
                int xg = x0 + g + kx - 1;
                bool p0 = (unsigned)xg < 32u;
                bool p1 = (unsigned)(xg + 8) < 32u;
                int sA = yA * 32 + xg;
                int sB = sA + 32;
                const float* xb = Xs + l4 * 1032;
                const float* wb = Ws + ((ky * 3 + kx) * 32 + l4) * 72 + g;
#pragma unroll
                for (int icq = 0; icq < 4; ++icq) {
                    const float* xp = xb + (icq * 8) * 1032;
                    float a0 = (yokA && p0) ? xp[sA]            : 0.f;
                    float a1 = (yokA && p1) ? xp[sA + 8]        : 0.f;
                    float a2 = (yokA && p0) ? xp[4 * 1032 + sA] : 0.f;
                    float a3 = (yokA && p1) ? xp[4 * 1032 + sA + 8] : 0.f;
                    float e0 = (yokB && p0) ? xp[sB]            : 0.f;
                    float e1 = (yokB && p1) ? xp[sB + 8]        : 0.f;
                    float e2 = (yokB && p0) ? xp[4 * 1032 + sB] : 0.f;
                    float e3 = (yokB && p1) ? xp[4 * 1032 + sB + 8] : 0.f;
                    const float* wq = wb + (icq * 8) * 72;
#pragma unroll
                    for (int j = 0; j < 8; ++j) {
                        float b0 = wq[8 * j];
                        float b1 = wq[4 * 72 + 8 * j];
                        mma_tf32(acc[0][j], a0, a1, a2, a3, b0, b1);
                        mma_tf32(acc[1][j], e0, e1, e2, e3, b0, b1);
                    }
                }
            }
        }
#pragma unroll
        for (int j = 0; j < 8; ++j)
#pragma unroll
            for (int i = 0; i < 4; ++i) {
                float m = fmaxf(acc[0][j][i], acc[1][j][i]);
                m = fmaxf(m, __shfl_xor_sync(0xffffffffu, m, 4));
                m = fmaxf(m + sb[8 * j + 2 * l4 + (i & 1)], 0.f);
                cs[j][i & 1] += m;
            }
    }

#pragma unroll
    for (int j = 0; j < 8; ++j)
#pragma unroll
        for (int i = 0; i < 2; ++i) {
            float v = cs[j][i];
            v += __shfl_xor_sync(0xffffffffu, v, 16);
            v += __shfl_xor_sync(0xffffffffu, v, 8);
            v += __shfl_xor_sync(0xffffffffu, v, 4);
            cs[j][i] = v;
        }
    if (g == 0) {
#pragma unroll
        for (int j = 0; j < 8; ++j) {
            red[wp * 64 + 8 * j + 2 * l4]     = cs[j][0];
            red[wp * 64 + 8 * j + 2 * l4 + 1] = cs[j][1];
        }
    }
    __syncthreads();
    if (tid < 64) {
        float s = 0.f;
#pragma unroll
        for (int ww = 0; ww < 8; ++ww) s += red[ww * 64 + tid];
        g_feat[n * 64 + tid] = s * (1.0f / 512.0f);
    }
}

// ---------------------------------------------------------------------------
// small kernels
// ---------------------------------------------------------------------------
__global__ void k_filler() { if (threadIdx.x < 32) g_fill[threadIdx.x] = 0.f; }

__global__ void __launch_bounds__(256) k_cnnfc(const float* __restrict__ fw,
                                               const float* __restrict__ fb) {
    __shared__ float sf[64];
    int n = blockIdx.x;
    if (threadIdx.x < 64) sf[threadIdx.x] = g_feat[n * 64 + threadIdx.x];
    __syncthreads();
    int j = threadIdx.x;
    if (j < VID_FEAT) {
        float acc = fb[j];
        const float* wr = fw + j * 64;
#pragma unroll
        for (int k = 0; k < 64; ++k) acc += sf[k] * wr[k];
        g_xc[(size_t)n * DQ + j] = acc;
    }
}

__global__ void k_audio(const float* __restrict__ a) {
    int i = blockIdx.x * 256 + threadIdx.x;
    if (i >= BQ * LQ * N_MFCC) return;
    int m = i % N_MFCC;
    int t = i / N_MFCC;
    g_xc[(size_t)t * DQ + VID_FEAT + m] = a[i];
}

__global__ void k_lastcol() {
    int i = blockIdx.x * 256 + threadIdx.x;
    if (i < BQ * DQ) {
        int b = i >> 8, d = i & 255;
        g_xb[i] = g_xc[(size_t)(b * LQ + LQ - 1) * DQ + d];
    }
}

// ---------------------------------------------------------------------------
// fused rmsnorm + in_proj GEMM: xz[T,1024] = rmsnorm(x)[T,256] @ in_w[1024,256]^T
// grid (16, ceil(T/64)); whole 64x256 A-tile staged + normalized in smem
// ---------------------------------------------------------------------------
#define IP_SMEM_BYTES ((256 * 65 + 16 * 68 + 64) * 4)

__global__ void __launch_bounds__(256) k_inproj(const float* __restrict__ x,
                                                const float* __restrict__ w_in,
                                                const float* __restrict__ norm_w,
                                                float* __restrict__ xz, int M) {
    extern __shared__ float sm[];
    float* At   = sm;                 // [c:256][r:64] stride 65
    float* Bsm  = At + 256 * 65;      // [16][68]
    float* sinv = Bsm + 16 * 68;      // 64
    int tid = threadIdx.x;
    int m0 = blockIdx.y * 64, n0 = blockIdx.x * 64;
    int lane = tid & 31, wp = tid >> 5;

    for (int r = 0; r < 64; ++r) {
        float v = (m0 + r < M) ? x[(size_t)(m0 + r) * DQ + tid] : 0.f;
        At[tid * 65 + r] = v;
    }
    __syncthreads();
    // rms per row: warp wp handles rows wp*8..wp*8+7
    for (int rr = 0; rr < 8; ++rr) {
        int r = wp * 8 + rr;
        float s = 0.f;
        for (int c = lane; c < 256; c += 32) {
            float v = At[c * 65 + r];
            s += v * v;
        }
#pragma unroll
        for (int off = 16; off > 0; off >>= 1) s += __shfl_xor_sync(~0u, s, off);
        if (lane == 0) sinv[r] = rsqrtf(s * (1.0f / DQ) + 1e-5f);
    }
    __syncthreads();
    float wn = norm_w[tid];
    for (int r = 0; r < 64; ++r) At[tid * 65 + r] *= sinv[r] * wn;
    __syncthreads();

    int ty = tid >> 4, tx = tid & 15;
    float acc[4][4] = {};
    for (int k0 = 0; k0 < 256; k0 += 16) {
        for (int i = tid; i < 1024; i += 256) {
            int r = i >> 4, kk = i & 15;
            Bsm[kk * 68 + r] = w_in[(size_t)(n0 + r) * DQ + k0 + kk];
        }
        __syncthreads();
#pragma unroll
        for (int kk = 0; kk < 16; ++kk) {
            const float* ar = At + (k0 + kk) * 65 + ty * 4;
            float4 bv = *reinterpret_cast<const float4*>(&Bsm[kk * 68 + tx * 4]);
            float a0 = ar[0], a1 = ar[1], a2 = ar[2], a3 = ar[3];
            float b[4] = {bv.x, bv.y, bv.z, bv.w};
#pragma unroll
            for (int j = 0; j < 4; ++j) {
                acc[0][j] += a0 * b[j];
                acc[1][j] += a1 * b[j];
                acc[2][j] += a2 * b[j];
                acc[3][j] += a3 * b[j];
            }
        }
        __syncthreads();
    }
#pragma unroll
    for (int i = 0; i < 4; ++i) {
        int r = m0 + ty * 4 + i;
        if (r >= M) continue;
#pragma unroll
        for (int j = 0; j < 4; ++j)
            xz[(size_t)r * 1024 + n0 + tx * 4 + j] = acc[i][j];
    }
}

// ---------------------------------------------------------------------------
// generic SGEMM: C[M,N] = A[M,K] @ B[N,K]^T (+bias) (+=C if accum)
// ---------------------------------------------------------------------------
__global__ void __launch_bounds__(256) k_gemm(const float* __restrict__ A, int lda,
                                              const float* __restrict__ Bw, int ldb,
                                              float* __restrict__ C, int ldc,
                                              int M, int N, int K,
                                              const float* __restrict__ bias,
                                              int accum) {
    __shared__ float As[16][68];
    __shared__ float Bs[16][68];
    int m0 = blockIdx.y * 64, n0 = blockIdx.x * 64;
    int ty = threadIdx.x >> 4, tx = threadIdx.x & 15;
    float acc[4][4] = {};
    for (int k0 = 0; k0 < K; k0 += 16) {
        for (int i = threadIdx.x; i < 1024; i += 256) {
            int r = i >> 4, kk = i & 15;
            int gk = k0 + kk;
            As[kk][r] = (m0 + r < M && gk < K) ? A[(size_t)(m0 + r) * lda + gk] : 0.f;
            Bs[kk][r] = (n0 + r < N && gk < K) ? Bw[(size_t)(n0 + r) * ldb + gk] : 0.f;
        }
        __syncthreads();
#pragma unroll
        for (int kk = 0; kk < 16; ++kk) {
            float4 av = *reinterpret_cast<const float4*>(&As[kk][ty * 4]);
            float4 bv = *reinterpret_cast<const float4*>(&Bs[kk][tx * 4]);
            float a[4] = {av.x, av.y, av.z, av.w};
            float b[4] = {bv.x, bv.y, bv.z, bv.w};
#pragma unroll
            for (int i = 0; i < 4; ++i)
#pragma unroll
                for (int j = 0; j < 4; ++j) acc[i][j] += a[i] * b[j];
        }
        __syncthreads();
    }
#pragma unroll
    for (int i = 0; i < 4; ++i) {
        int r = m0 + ty * 4 + i;
        if (r >= M) continue;
#pragma unroll
        for (int j = 0; j < 4; ++j) {
            int c = n0 + tx * 4 + j;
            if (c >= N) continue;
            float v = acc[i][j];
            if (bias) v += bias[c];
            if (accum) v += C[(size_t)r * ldc + c];
            C[(size_t)r * ldc + c] = v;
        }
    }
}

// ---------------------------------------------------------------------------
// causal depthwise conv4 + silu
// ---------------------------------------------------------------------------
__global__ void k_convsilu(const float* __restrict__ cw,
                           const float* __restrict__ cb, int T, int Lc) {
    int i = blockIdx.x * 256 + threadIdx.x;
    if (i >= T * EDQ) return;
    int t = i >> 9, e = i & 511;
    int l = t % Lc;
    float acc = cb[e];
#pragma unroll
    for (int k = 0; k < 4; ++k) {
        int li = l + k - 3;
        if (li >= 0) acc += g_xz[(size_t)(t + k - 3) * 1024 + e] * cw[e * 4 + k];
    }
    acc = acc / (1.f + __expf(-acc));
    g_xcs[i] = acc;
}

// ---------------------------------------------------------------------------
// fused scan: dt-proj + softplus + selective scan + D*x + silu(z) gate
// thread per (b, e) channel, 16 states in registers
// ---------------------------------------------------------------------------
__global__ void __launch_bounds__(128) k_scan_f(const float* __restrict__ A_log,
                                                const float* __restrict__ Dp,
                                                const float* __restrict__ dt_w,
                                                const float* __restrict__ dt_b,
                                                int Lc) {
    int e = blockIdx.x * 128 + threadIdx.x;
    int b = blockIdx.y;
    float negA[NSTQ], dtw[DTRQ], h[NSTQ];
#pragma unroll
    for (int n = 0; n < NSTQ; ++n) negA[n] = -__expf(A_log[e * NSTQ + n]);
#pragma unroll
    for (int n = 0; n < DTRQ; ++n) dtw[n] = dt_w[e * DTRQ + n];
    float dtb = dt_b[e];
    float Dv = Dp[e];
#pragma unroll
    for (int n = 0; n < NSTQ; ++n) h[n] = 0.f;
    for (int t = 0; t < Lc; ++t) {
        size_t idx = (size_t)(b * Lc + t);
        const float* bc = g_dbc + idx * 48;
        float draw = dtb;
#pragma unroll
        for (int n = 0; n < DTRQ; ++n) draw += __ldg(bc + n) * dtw[n];
        float dlt = (draw > 20.f) ? draw : log1pf(__expf(draw));
        float xv = g_xcs[idx * EDQ + e];
        float z  = g_xz[idx * 1024 + EDQ + e];
        float dx = dlt * xv;
        float y = 0.f;
#pragma unroll
        for (int n = 0; n < NSTQ; ++n) {
            float hn = __expf(dlt * negA[n]) * h[n] + dx * __ldg(bc + 16 + n);
            h[n] = hn;
            y += hn * __ldg(bc + 32 + n);
        }
        float sz = z / (1.f + __expf(-z));
        g_ys[idx * EDQ + e] = (y + Dv * xv) * sz;
    }
}

// ---------------------------------------------------------------------------
// whole backward Mamba layer (T=1 per batch): one block per batch element
// scan at T=1: h = delta*B*x  =>  y = delta*x*(B.C) + D*x
// ---------------------------------------------------------------------------
__global__ void __launch_bounds__(256) k_bwd_layer(
    const float* __restrict__ norm_w, const float* __restrict__ in_w,
    const float* __restrict__ conv_w, const float* __restrict__ conv_b,
    const float* __restrict__ xp_w,  const float* __restrict__ dt_w,
    const float* __restrict__ dt_b,  const float* __restrict__ Dp,
    const float* __restrict__ out_w) {
    __shared__ float sx[256], sxn[256], sxcs[512], sz[512], sdbc[48], sys[512];
    __shared__ float sred[8];
    __shared__ float sbc;
    int b = blockIdx.x, tid = threadIdx.x;
    int lane = tid & 31, wp = tid >> 5;

    float xv = g_xb[b * DQ + tid];
    sx[tid] = xv;
    float s = xv * xv;
#pragma unroll
    for (int off = 16; off > 0; off >>= 1) s += __shfl_xor_sync(~0u, s, off);
    if (lane == 0) sred[wp] = s;
    __syncthreads();
    float tot = sred[0] + sred[1] + sred[2] + sred[3] +
                sred[4] + sred[5] + sred[6] + sred[7];
    float inv = rsqrtf(tot * (1.0f / DQ) + 1e-5f);
    sxn[tid] = xv * inv * norm_w[tid];
    __syncthreads();

    // in_proj (1024 outputs) + causal conv (l=0 keeps only tap 3) + silu
    for (int q = 0; q < 4; ++q) {
        int o = q * 256 + tid;
        float acc = 0.f;
        const float* wr = in_w + (size_t)o * DQ;
        for (int k = 0; k < 256; ++k) acc += sxn[k] * wr[k];
        if (o < EDQ) {
            float v = acc * conv_w[o * 4 + 3] + conv_b[o];
            sxcs[o] = v / (1.f + __expf(-v));
        } else {
            sz[o - EDQ] = acc;
        }
    }
    __syncthreads();

    // x_proj: 48 outputs, warp wp handles rows wp*6..wp*6+5
    for (int rr = 0; rr < 6; ++rr) {
        int r = wp * 6 + rr;
        float a = 0.f;
        const float* wr = xp_w + (size_t)r * EDQ;
        for (int k = lane; k < 512; k += 32) a += sxcs[k] * wr[k];
#pragma unroll
        for (int off = 16; off > 0; off >>= 1) a += __shfl_xor_sync(~0u, a, off);
        if (lane == 0) sdbc[r] = a;
    }
    __syncthreads();
    if (tid == 0) {
        float a = 0.f;
#pragma unroll
        for (int n = 0; n < NSTQ; ++n) a += sdbc[16 + n] * sdbc[32 + n];
        sbc = a;
    }
    __syncthreads();

    // delta + y + gate
    for (int q = 0; q < 2; ++q) {
        int e = q * 256 + tid;
        float d = dt_b[e];
        const float* wr = dt_w + e * DTRQ;
#pragma unroll
        for (int n = 0; n < DTRQ; ++n) d += sdbc[n] * wr[n];
        d = (d > 20.f) ? d : log1pf(__expf(d));
        float xc_ = sxcs[e];
        float y = d * xc_ * sbc + Dp[e] * xc_;
        float z = sz[e];
        sys[e] = y * (z / (1.f + __expf(-z)));
    }
    __syncthreads();

    // out_proj + residual
    float o = sx[tid];
    const float* wr = out_w + (size_t)tid * EDQ;
    for (int k = 0; k < 512; ++k) o += sys[k] * wr[k];
    g_xb[b * DQ + tid] = o;
}

// ---------------------------------------------------------------------------
// head: concat(xc[:, -1], xb) -> fc1 -> fc2
// ---------------------------------------------------------------------------
__global__ void __launch_bounds__(256) k_head(const float* __restrict__ fc_w,
                                              const float* __restrict__ fc_b,
                                              const float* __restrict__ fc2_w,
                                              const float* __restrict__ fc2_b,
                                              float* __restrict__ out) {
    __shared__ float sxl[512], sfc1[256];
    int b = blockIdx.x, tid = threadIdx.x;
    sxl[tid]       = g_xc[(size_t)(b * LQ + LQ - 1) * DQ + tid];
    sxl[256 + tid] = g_xb[b * DQ + tid];
    __syncthreads();
    float a = fc_b[tid];
    const float* wr = fc_w + (size_t)tid * (2 * DQ);
    for (int k = 0; k < 512; ++k) a += sxl[k] * wr[k];
    sfc1[tid] = a;
    __syncthreads();
    if (tid < 2) {
        float o = fc2_b[tid];
        const float* wr2 = fc2_w + tid * DQ;
        for (int k = 0; k < 256; ++k) o += sfc1[k] * wr2[k];
        out[b * 2 + tid] = o;
    }
}

// ---------------------------------------------------------------------------
// Host-side driver
// ---------------------------------------------------------------------------
static float* symf(const void* s) {
    void* p = nullptr;
    cudaGetSymbolAddress(&p, s);
    return (float*)p;
}

static void fwd_layer(float* x, const float* const* p, int l) {
    const float* norm_w = p[0] + (size_t)l * DQ;
    const float* in_w   = p[1] + (size_t)l * 2 * EDQ * DQ;
    const float* conv_w = p[2] + (size_t)l * EDQ * 4;
    const float* conv_b = p[3] + (size_t)l * EDQ;
    const float* xp_w   = p[4] + (size_t)l * (DTRQ + 2 * NSTQ) * EDQ;
    const float* dt_w   = p[5] + (size_t)l * EDQ * DTRQ;
    const float* dt_b   = p[6] + (size_t)l * EDQ;
    const float* A_log  = p[7] + (size_t)l * EDQ * NSTQ;
    const float* Dp     = p[8] + (size_t)l * EDQ;
    const float* out_w  = p[9] + (size_t)l * DQ * EDQ;

    const int T = NIMG;
    float* xz  = symf(g_xz);
    float* xcs = symf(g_xcs);
    float* dbc = symf(g_dbc);
    float* ys  = symf(g_ys);

    k_inproj<<<dim3(16, 16), 256, IP_SMEM_BYTES>>>(x, in_w, norm_w, xz, T);
    k_convsilu<<<(T * EDQ + 255) / 256, 256>>>(conv_w, conv_b, T, LQ);
    k_gemm<<<dim3(1, 16), 256>>>(xcs, EDQ, xp_w, EDQ, dbc, 48, T, 48, EDQ, nullptr, 0);
    k_scan_f<<<dim3(EDQ / 128, BQ), 128>>>(A_log, Dp, dt_w, dt_b, LQ);
    k_gemm<<<dim3(4, 16), 256>>>(ys, EDQ, out_w, EDQ, x, DQ, T, DQ, EDQ, nullptr, 1);
}

extern "C" void kernel_launch(void* const* d_in, const int* in_sizes, int n_in,
                              void* d_out, int out_size) {
    const float* video = (const float*)d_in[0];
    const float* audio = (const float*)d_in[1];
    const float* c1w = (const float*)d_in[2];
    const float* c1b = (const float*)d_in[3];
    const float* c2w = (const float*)d_in[4];
    const float* c2b = (const float*)d_in[5];
    const float* fcw = (const float*)d_in[6];
    const float* fcb = (const float*)d_in[7];
    const float* fwdp[10];
    const float* bwdp[10];
    for (int i = 0; i < 10; ++i) fwdp[i] = (const float*)d_in[8 + i];
    for (int i = 0; i < 10; ++i) bwdp[i] = (const float*)d_in[18 + i];
    const float* fc_w  = (const float*)d_in[28];
    const float* fc_b  = (const float*)d_in[29];
    const float* fc2_w = (const float*)d_in[30];
    const float* fc2_b = (const float*)d_in[31];
    float* out = (float*)d_out;

    cudaFuncSetAttribute(k_conv1_mma, cudaFuncAttributeMaxDynamicSharedMemorySize,
                         C1_SMEM_BYTES);
    cudaFuncSetAttribute(k_conv2_mma, cudaFuncAttributeMaxDynamicSharedMemorySize,
                         C2_SMEM_BYTES);
    cudaFuncSetAttribute(k_inproj, cudaFuncAttributeMaxDynamicSharedMemorySize,
                         IP_SMEM_BYTES);

    // launch order engineered so the ncu capture (our 4th launch) = k_conv2_mma
    k_audio<<<(BQ * LQ * N_MFCC + 255) / 256, 256>>>(audio);          // 1
    k_conv1_mma<<<NIMG, 256, C1_SMEM_BYTES>>>(video, c1w, c1b);       // 2
    k_filler<<<1, 32>>>();                                            // 3
    k_conv2_mma<<<NIMG, 256, C2_SMEM_BYTES>>>(c2w, c2b);              // 4 (captured)
    k_cnnfc<<<NIMG, 256>>>(fcw, fcb);                                 // 5
    k_lastcol<<<(BQ * DQ + 255) / 256, 256>>>();                      // 6

    float* xc = symf(g_xc);

    for (int l = 0; l < NLQ; ++l) fwd_layer(xc, fwdp, l);             // 7..26

    for (int l = 0; l < NLQ; ++l) {                                   // 27..30
        const float* p[10];
        p[0] = bwdp[0] + (size_t)l * DQ;
        p[1] = bwdp[1] + (size_t)l * 2 * EDQ * DQ;
        p[2] = bwdp[2] + (size_t)l * EDQ * 4;
        p[3] = bwdp[3] + (size_t)l * EDQ;
        p[4] = bwdp[4] + (size_t)l * (DTRQ + 2 * NSTQ) * EDQ;
        p[5] = bwdp[5] + (size_t)l * EDQ * DTRQ;
        p[6] = bwdp[6] + (size_t)l * EDQ;
        p[7] = bwdp[8] + (size_t)l * EDQ;       // D
        p[8] = bwdp[9] + (size_t)l * DQ * EDQ;  // out_w
        k_bwd_layer<<<BQ, 256>>>(p[0], p[1], p[2], p[3], p[4], p[5], p[6],
                                 p[7], p[8]);
    }

    k_head<<<BQ, 256>>>(fc_w, fc_b, fc2_w, fc2_b, out);               // 31
}

// round 4
// speedup vs baseline: 1.0357x; 1.0357x over previous
#include <cuda_runtime.h>
#include <math.h>
#include <stdint.h>

// ---------------------------------------------------------------------------
// Problem constants
// ---------------------------------------------------------------------------
#define BQ      8
#define LQ      128
#define NIMG    1024          // BQ * LQ
#define DQ      256           // VID_FEAT + N_MFCC
#define EDQ     512           // 2*DQ
#define NSTQ    16
#define DTRQ    16
#define NLQ     4
#define VID_FEAT 196
#define N_MFCC   60

// ---------------------------------------------------------------------------
// Scratch (device globals; allocation-free per harness rules)
// ---------------------------------------------------------------------------
__device__ float g_pool1[(size_t)NIMG * 32 * 32 * 32];   // conv1+pool out
__device__ float g_feat [NIMG * 64];                     // conv2+pool+mean out
__device__ float g_xc   [NIMG * DQ];                     // concat feats / fwd stream
__device__ float g_xn   [NIMG * DQ];                     // rmsnorm out
__device__ float g_xz   [NIMG * 2 * EDQ];                // in_proj out (x | z)
__device__ float g_xcs  [NIMG * EDQ];                    // conv+silu out
__device__ float g_dbc  [NIMG * 48];                     // x_proj out (dt|B|C)
__device__ float g_ys   [NIMG * EDQ];                    // scan out (gated)
__device__ float g_xb   [BQ * DQ];                       // bwd mamba stream
__device__ float g_fill [32];                            // filler target

// ---------------------------------------------------------------------------
// tf32 mma helpers
// ---------------------------------------------------------------------------
__device__ __forceinline__ void mma_tf32(float* c, float a0, float a1,
                                         float a2, float a3,
                                         float b0, float b1) {
    asm volatile(
        "mma.sync.aligned.m16n8k8.row.col.f32.tf32.tf32.f32 "
        "{%0,%1,%2,%3}, {%4,%5,%6,%7}, {%8,%9}, {%0,%1,%2,%3};"
        : "+f"(c[0]), "+f"(c[1]), "+f"(c[2]), "+f"(c[3])
        : "r"(__float_as_uint(a0)), "r"(__float_as_uint(a1)),
          "r"(__float_as_uint(a2)), "r"(__float_as_uint(a3)),
          "r"(__float_as_uint(b0)), "r"(__float_as_uint(b1)));
}

__device__ __forceinline__ float to_tf32(float v) {
    uint32_t u;
    asm("cvt.rna.tf32.f32 %0, %1;" : "=r"(u) : "f"(v));
    return __uint_as_float(u);
}

// ---------------------------------------------------------------------------
// conv1 via tf32 mma implicit GEMM + bias + relu + maxpool2, pooled store
// 512 threads (16 warps): xh = wp&3, yp = wp>>2, 8 chunks
// ---------------------------------------------------------------------------
#define C1_SMEM_FLOATS (12288 + 32 * 40 + 32)
#define C1_SMEM_BYTES  (C1_SMEM_FLOATS * 4)

__global__ void __launch_bounds__(512) k_conv1_mma(const float* __restrict__ video,
                                                   const float* __restrict__ w,
                                                   const float* __restrict__ bias) {
    extern __shared__ float sm[];
    float* Xs = sm;                  // 12288
    float* Ws = Xs + 12288;          // 32*40
    float* sb = Ws + 32 * 40;        // 32
    int n = blockIdx.x;
    int tid = threadIdx.x;

    const float* img = video + (size_t)n * 12288;
    for (int i = tid; i < 12288; i += 512) Xs[i] = to_tf32(img[i]);
    for (int i = tid; i < 1280;  i += 512) Ws[i] = 0.f;
    if (tid < 32) sb[tid] = bias[tid];
    __syncthreads();
    for (int i = tid; i < 864; i += 512) {
        int oc = i / 27, r = i % 27;          // r = ic*9 + ky*3 + kx = k
        Ws[r * 40 + oc] = to_tf32(w[i]);
    }
    __syncthreads();

    int lane = tid & 31, wp = tid >> 5;
    int g = lane >> 2, l4 = lane & 3;
    int xh = wp & 3, yp = wp >> 2;            // 4 x-segments, 4 y-pairs
    int x0 = xh * 16;

    int ky0[4], kx0[4], ic0[4];
    int ky1[4], kx1[4], ic1[4];
#pragma unroll
    for (int kk = 0; kk < 4; ++kk) {
        int k0 = kk * 8 + l4;
        int k1 = k0 + 4;
        if (k0 < 27) { ic0[kk] = (k0 / 9) * 4096; int t = k0 % 9; ky0[kk] = t / 3; kx0[kk] = t % 3; }
        else         { ic0[kk] = 0; ky0[kk] = 1; kx0[kk] = 1; }
        if (k1 < 27) { ic1[kk] = (k1 / 9) * 4096; int t = k1 % 9; ky1[kk] = t / 3; kx1[kk] = t % 3; }
        else         { ic1[kk] = 0; ky1[kk] = 1; kx1[kk] = 1; }
    }

    for (int chunk = 0; chunk < 8; ++chunk) {
        int y = chunk * 8 + yp * 2;           // rows y, y+1 (pool pair)
        float acc[2][4][4];
#pragma unroll
        for (int t = 0; t < 2; ++t)
#pragma unroll
            for (int j = 0; j < 4; ++j)
#pragma unroll
                for (int i = 0; i < 4; ++i) acc[t][j][i] = 0.f;

#pragma unroll
        for (int kk = 0; kk < 4; ++kk) {
            int yA0 = y + ky0[kk] - 1,  yA1 = y + ky1[kk] - 1;
            int xgA = x0 + g + kx0[kk] - 1;
            int xgB = x0 + g + kx1[kk] - 1;
            bool pA0 = (unsigned)xgA < 64u, pA1 = (unsigned)(xgA + 8) < 64u;
            bool pB0 = (unsigned)xgB < 64u, pB1 = (unsigned)(xgB + 8) < 64u;
            bool y00 = (unsigned)yA0 < 64u, y01 = (unsigned)(yA0 + 1) < 64u;
            bool y10 = (unsigned)yA1 < 64u, y11 = (unsigned)(yA1 + 1) < 64u;
            const float* xb0 = Xs + ic0[kk] + yA0 * 64;
            const float* xb1 = Xs + ic1[kk] + yA1 * 64;
            float a0 = (y00 && pA0) ? xb0[xgA]          : 0.f;
            float a1 = (y00 && pA1) ? xb0[xgA + 8]      : 0.f;
            float a2 = (y10 && pB0) ? xb1[xgB]          : 0.f;
            float a3 = (y10 && pB1) ? xb1[xgB + 8]      : 0.f;
            float e0 = (y01 && pA0) ? xb0[64 + xgA]     : 0.f;
            float e1 = (y01 && pA1) ? xb0[64 + xgA + 8] : 0.f;
            float e2 = (y11 && pB0) ? xb1[64 + xgB]     : 0.f;
            float e3 = (y11 && pB1) ? xb1[64 + xgB + 8] : 0.f;
            const float* w0 = Ws + (kk * 8 + l4) * 40 + g;
            const float* w1 = w0 + 4 * 40;
#pragma unroll
            for (int j = 0; j < 4; ++j) {
                float b0 = w0[8 * j];
                float b1 = w1[8 * j];
                mma_tf32(acc[0][j], a0, a1, a2, a3, b0, b1);
                mma_tf32(acc[1][j], e0, e1, e2, e3, b0, b1);
            }
        }

        int py = chunk * 4 + yp;
#pragma unroll
        for (int j = 0; j < 4; ++j)
#pragma unroll
            for (int i = 0; i < 4; ++i) {
                float m = fmaxf(acc[0][j][i], acc[1][j][i]);
                m = fmaxf(m, __shfl_xor_sync(0xffffffffu, m, 4));
                int oc = 8 * j + 2 * l4 + (i & 1);
                m = fmaxf(m + sb[oc], 0.f);
                if ((g & 1) == 0) {
                    int px = ((x0 + g) >> 1) + ((i >= 2) ? 4 : 0);
                    g_pool1[(((size_t)n * 32 + oc) << 10) + (py << 5) + px] = m;
                }
            }
    }
}

// ---------------------------------------------------------------------------
// conv2 via tf32 mma implicit GEMM + relu + maxpool2 + mean
// 512 threads (16 warps): ypair = wp>>1 (0..7), xh = wp&1, 2 c-iters
// ---------------------------------------------------------------------------
#define XS_FLOATS (32 * 1032)
#define WS_FLOATS (288 * 72)
#define C2_SMEM_BYTES ((XS_FLOATS + WS_FLOATS + 64 + 1024) * 4)

__global__ void __launch_bounds__(512) k_conv2_mma(const float* __restrict__ w,
                                                   const float* __restrict__ bias) {
    extern __shared__ float sm[];
    float* Xs  = sm;
    float* Ws  = Xs + XS_FLOATS;
    float* sb  = Ws + WS_FLOATS;
    float* red = sb + 64;            // 16*64
    int n = blockIdx.x;
    int tid = threadIdx.x;

    const float* src = g_pool1 + (size_t)n * 32768;
    for (int i = tid; i < 32768; i += 512) {
        int ic = i >> 10, s = i & 1023;
        Xs[ic * 1032 + s] = to_tf32(src[i]);
    }
    for (int i = tid; i < 18432; i += 512) {
        int oc = i / 288, r = i % 288;
        int ic = r / 9, kk = r % 9;
        Ws[(kk * 32 + ic) * 72 + oc] = to_tf32(w[i]);
    }
    if (tid < 64) sb[tid] = bias[tid];
    __syncthreads();

    int lane = tid & 31, wp = tid >> 5;
    int g = lane >> 2, l4 = lane & 3;
    int ypair = wp >> 1, xh = wp & 1;
    int x0 = xh * 16;

    float cs[8][2];
#pragma unroll
    for (int j = 0; j < 8; ++j) { cs[j][0] = 0.f; cs[j][1] = 0.f; }

    for (int c = 0; c < 2; ++c) {
        int y = c * 16 + ypair * 2;
        float acc[2][8][4];
#pragma unroll
        for (int t = 0; t < 2; ++t)
#pragma unroll
            for (int j = 0; j < 8; ++j)
#pragma unroll
                for (int i = 0; i < 4; ++i) acc[t][j][i] = 0.f;

#pragma unroll
        for (int ky = 0; ky < 3; ++ky) {
            int yA = y + ky - 1;
            int yB = yA + 1;
            bool yokA = (unsigned)yA < 32u;
            bool yokB = (unsigned)yB < 32u;
#pragma unroll
            for (int kx = 0; kx < 3; ++kx) {
                int xg = x0 + g + kx - 1;
                bool p0 = (unsigned)xg < 32u;
                bool p1 = (unsigned)(xg + 8) < 32u;
                int sA = yA * 32 + xg;
                int sB = sA + 32;
                const float* xb = Xs + l4 * 1032;
                const float* wb = Ws + ((ky * 3 + kx) * 32 + l4) * 72 + g;
#pragma unroll
                for (int icq = 0; icq < 4; ++icq) {
                    const float* xp = xb + (icq * 8) * 1032;
                    float a0 = (yokA && p0) ? xp[sA]            : 0.f;
                    float a1 = (yokA && p1) ? xp[sA + 8]        : 0.f;
                    float a2 = (yokA && p0) ? xp[4 * 1032 + sA] : 0.f;
                    float a3 = (yokA && p1) ? xp[4 * 1032 + sA + 8] : 0.f;
                    float e0 = (yokB && p0) ? xp[sB]            : 0.f;
                    float e1 = (yokB && p1) ? xp[sB + 8]        : 0.f;
                    float e2 = (yokB && p0) ? xp[4 * 1032 + sB] : 0.f;
                    float e3 = (yokB && p1) ? xp[4 * 1032 + sB + 8] : 0.f;
                    const float* wq = wb + (icq * 8) * 72;
#pragma unroll
                    for (int j = 0; j < 8; ++j) {
                        float b0 = wq[8 * j];
                        float b1 = wq[4 * 72 + 8 * j];
                        mma_tf32(acc[0][j], a0, a1, a2, a3, b0, b1);
                        mma_tf32(acc[1][j], e0, e1, e2, e3, b0, b1);
                    }
                }
            }
        }
#pragma unroll
        for (int j = 0; j < 8; ++j)
#pragma unroll
            for (int i = 0; i < 4; ++i) {
                float m = fmaxf(acc[0][j][i], acc[1][j][i]);
                m = fmaxf(m, __shfl_xor_sync(0xffffffffu, m, 4));
                m = fmaxf(m + sb[8 * j + 2 * l4 + (i & 1)], 0.f);
                cs[j][i & 1] += m;
            }
    }

#pragma unroll
    for (int j = 0; j < 8; ++j)
#pragma unroll
        for (int i = 0; i < 2; ++i) {
            float v = cs[j][i];
            v += __shfl_xor_sync(0xffffffffu, v, 16);
            v += __shfl_xor_sync(0xffffffffu, v, 8);
            v += __shfl_xor_sync(0xffffffffu, v, 4);
            cs[j][i] = v;
        }
    if (g == 0) {
#pragma unroll
        for (int j = 0; j < 8; ++j) {
            red[wp * 64 + 8 * j + 2 * l4]     = cs[j][0];
            red[wp * 64 + 8 * j + 2 * l4 + 1] = cs[j][1];
        }
    }
    __syncthreads();
    if (tid < 64) {
        float s = 0.f;
#pragma unroll
        for (int ww = 0; ww < 16; ++ww) s += red[ww * 64 + tid];
        g_feat[n * 64 + tid] = s * (1.0f / 512.0f);
    }
}

// ---------------------------------------------------------------------------
// small kernels
// ---------------------------------------------------------------------------
__global__ void k_filler() { if (threadIdx.x < 32) g_fill[threadIdx.x] = 0.f; }

__global__ void __launch_bounds__(256) k_cnnfc(const float* __restrict__ fw,
                                               const float* __restrict__ fb) {
    __shared__ float sf[64];
    int n = blockIdx.x;
    if (threadIdx.x < 64) sf[threadIdx.x] = g_feat[n * 64 + threadIdx.x];
    __syncthreads();
    int j = threadIdx.x;
    if (j < VID_FEAT) {
        float acc = fb[j];
        const float* wr = fw + j * 64;
#pragma unroll
        for (int k = 0; k < 64; ++k) acc += sf[k] * wr[k];
        g_xc[(size_t)n * DQ + j] = acc;
    }
}

__global__ void k_audio(const float* __restrict__ a) {
    int i = blockIdx.x * 256 + threadIdx.x;
    if (i >= BQ * LQ * N_MFCC) return;
    int m = i % N_MFCC;
    int t = i / N_MFCC;
    g_xc[(size_t)t * DQ + VID_FEAT + m] = a[i];
}

__global__ void k_lastcol() {
    int i = blockIdx.x * 256 + threadIdx.x;
    if (i < BQ * DQ) {
        int b = i >> 8, d = i & 255;
        g_xb[i] = g_xc[(size_t)(b * LQ + LQ - 1) * DQ + d];
    }
}

// ---------------------------------------------------------------------------
// RMSNorm over D=256, one block per token
// ---------------------------------------------------------------------------
__global__ void __launch_bounds__(256) k_rms(const float* __restrict__ x,
                                             const float* __restrict__ w,
                                             float* __restrict__ out) {
    int t = blockIdx.x;
    float v = x[(size_t)t * DQ + threadIdx.x];
    float s = v * v;
#pragma unroll
    for (int off = 16; off > 0; off >>= 1) s += __shfl_xor_sync(~0u, s, off);
    __shared__ float red[8];
    if ((threadIdx.x & 31) == 0) red[threadIdx.x >> 5] = s;
    __syncthreads();
    float tot = red[0] + red[1] + red[2] + red[3] +
                red[4] + red[5] + red[6] + red[7];
    float inv = rsqrtf(tot * (1.0f / DQ) + 1e-5f);
    out[(size_t)t * DQ + threadIdx.x] = v * inv * w[threadIdx.x];
}

// ---------------------------------------------------------------------------
// generic SGEMM: C[M,N] = A[M,K] @ B[N,K]^T (+bias) (+=C if accum)
// ---------------------------------------------------------------------------
__global__ void __launch_bounds__(256) k_gemm(const float* __restrict__ A, int lda,
                                              const float* __restrict__ Bw, int ldb,
                                              float* __restrict__ C, int ldc,
                                              int M, int N, int K,
                                              const float* __restrict__ bias,
                                              int accum) {
    __shared__ float As[16][68];
    __shared__ float Bs[16][68];
    int m0 = blockIdx.y * 64, n0 = blockIdx.x * 64;
    int ty = threadIdx.x >> 4, tx = threadIdx.x & 15;
    float acc[4][4] = {};
    for (int k0 = 0; k0 < K; k0 += 16) {
        for (int i = threadIdx.x; i < 1024; i += 256) {
            int r = i >> 4, kk = i & 15;
            int gk = k0 + kk;
            As[kk][r] = (m0 + r < M && gk < K) ? A[(size_t)(m0 + r) * lda + gk] : 0.f;
            Bs[kk][r] = (n0 + r < N && gk < K) ? Bw[(size_t)(n0 + r) * ldb + gk] : 0.f;
        }
        __syncthreads();
#pragma unroll
        for (int kk = 0; kk < 16; ++kk) {
            float4 av = *reinterpret_cast<const float4*>(&As[kk][ty * 4]);
            float4 bv = *reinterpret_cast<const float4*>(&Bs[kk][tx * 4]);
            float a[4] = {av.x, av.y, av.z, av.w};
            float b[4] = {bv.x, bv.y, bv.z, bv.w};
#pragma unroll
            for (int i = 0; i < 4; ++i)
#pragma unroll
                for (int j = 0; j < 4; ++j) acc[i][j] += a[i] * b[j];
        }
        __syncthreads();
    }
#pragma unroll
    for (int i = 0; i < 4; ++i) {
        int r = m0 + ty * 4 + i;
        if (r >= M) continue;
#pragma unroll
        for (int j = 0; j < 4; ++j) {
            int c = n0 + tx * 4 + j;
            if (c >= N) continue;
            float v = acc[i][j];
            if (bias) v += bias[c];
            if (accum) v += C[(size_t)r * ldc + c];
            C[(size_t)r * ldc + c] = v;
        }
    }
}

// ---------------------------------------------------------------------------
// causal depthwise conv4 + silu
// ---------------------------------------------------------------------------
__global__ void k_convsilu(const float* __restrict__ cw,
                           const float* __restrict__ cb, int T, int Lc) {
    int i = blockIdx.x * 256 + threadIdx.x;
    if (i >= T * EDQ) return;
    int t = i >> 9, e = i & 511;
    int l = t % Lc;
    float acc = cb[e];
#pragma unroll
    for (int k = 0; k < 4; ++k) {
        int li = l + k - 3;
        if (li >= 0) acc += g_xz[(size_t)(t + k - 3) * 1024 + e] * cw[e * 4 + k];
    }
    acc = acc / (1.f + __expf(-acc));
    g_xcs[i] = acc;
}

// ---------------------------------------------------------------------------
// fused scan: dt-proj + softplus + selective scan + D*x + silu(z) gate
// ---------------------------------------------------------------------------
__global__ void __launch_bounds__(128) k_scan_f(const float* __restrict__ A_log,
                                                const float* __restrict__ Dp,
                                                const float* __restrict__ dt_w,
                                                const float* __restrict__ dt_b,
                                                int Lc) {
    int e = blockIdx.x * 128 + threadIdx.x;
    int b = blockIdx.y;
    float negA[NSTQ], dtw[DTRQ], h[NSTQ];
#pragma unroll
    for (int n = 0; n < NSTQ; ++n) negA[n] = -__expf(A_log[e * NSTQ + n]);
#pragma unroll
    for (int n = 0; n < DTRQ; ++n) dtw[n] = dt_w[e * DTRQ + n];
    float dtb = dt_b[e];
    float Dv = Dp[e];
#pragma unroll
    for (int n = 0; n < NSTQ; ++n) h[n] = 0.f;
    for (int t = 0; t < Lc; ++t) {
        size_t idx = (size_t)(b * Lc + t);
        const float* bc = g_dbc + idx * 48;
        float draw = dtb;
#pragma unroll
        for (int n = 0; n < DTRQ; ++n) draw += __ldg(bc + n) * dtw[n];
        float dlt = (draw > 20.f) ? draw : log1pf(__expf(draw));
        float xv = g_xcs[idx * EDQ + e];
        float z  = g_xz[idx * 1024 + EDQ + e];
        float dx = dlt * xv;
        float y = 0.f;
#pragma unroll
        for (int n = 0; n < NSTQ; ++n) {
            float hn = __expf(dlt * negA[n]) * h[n] + dx * __ldg(bc + 16 + n);
            h[n] = hn;
            y += hn * __ldg(bc + 32 + n);
        }
        float sz = z / (1.f + __expf(-z));
        g_ys[idx * EDQ + e] = (y + Dv * xv) * sz;
    }
}

// ---------------------------------------------------------------------------
// whole backward Mamba layer (T=1 per batch): one block per batch element
// ---------------------------------------------------------------------------
__global__ void __launch_bounds__(256) k_bwd_layer(
    const float* __restrict__ norm_w, const float* __restrict__ in_w,
    const float* __restrict__ conv_w, const float* __restrict__ conv_b,
    const float* __restrict__ xp_w,  const float* __restrict__ dt_w,
    const float* __restrict__ dt_b,  const float* __restrict__ Dp,
    const float* __restrict__ out_w) {
    __shared__ float sx[256], sxn[256], sxcs[512], sz[512], sdbc[48], sys[512];
    __shared__ float sred[8];
    __shared__ float sbc;
    int b = blockIdx.x, tid = threadIdx.x;
    int lane = tid & 31, wp = tid >> 5;

    float xv = g_xb[b * DQ + tid];
    sx[tid] = xv;
    float s = xv * xv;
#pragma unroll
    for (int off = 16; off > 0; off >>= 1) s += __shfl_xor_sync(~0u, s, off);
    if (lane == 0) sred[wp] = s;
    __syncthreads();
    float tot = sred[0] + sred[1] + sred[2] + sred[3] +
                sred[4] + sred[5] + sred[6] + sred[7];
    float inv = rsqrtf(tot * (1.0f / DQ) + 1e-5f);
    sxn[tid] = xv * inv * norm_w[tid];
    __syncthreads();

    for (int q = 0; q < 4; ++q) {
        int o = q * 256 + tid;
        float acc = 0.f;
        const float* wr = in_w + (size_t)o * DQ;
        for (int k = 0; k < 256; ++k) acc += sxn[k] * wr[k];
        if (o < EDQ) {
            float v = acc * conv_w[o * 4 + 3] + conv_b[o];
            sxcs[o] = v / (1.f + __expf(-v));
        } else {
            sz[o - EDQ] = acc;
        }
    }
    __syncthreads();

    for (int rr = 0; rr < 6; ++rr) {
        int r = wp * 6 + rr;
        float a = 0.f;
        const float* wr = xp_w + (size_t)r * EDQ;
        for (int k = lane; k < 512; k += 32) a += sxcs[k] * wr[k];
#pragma unroll
        for (int off = 16; off > 0; off >>= 1) a += __shfl_xor_sync(~0u, a, off);
        if (lane == 0) sdbc[r] = a;
    }
    __syncthreads();
    if (tid == 0) {
        float a = 0.f;
#pragma unroll
        for (int n = 0; n < NSTQ; ++n) a += sdbc[16 + n] * sdbc[32 + n];
        sbc = a;
    }
    __syncthreads();

    for (int q = 0; q < 2; ++q) {
        int e = q * 256 + tid;
        float d = dt_b[e];
        const float* wr = dt_w + e * DTRQ;
#pragma unroll
        for (int n = 0; n < DTRQ; ++n) d += sdbc[n] * wr[n];
        d = (d > 20.f) ? d : log1pf(__expf(d));
        float xc_ = sxcs[e];
        float y = d * xc_ * sbc + Dp[e] * xc_;
        float z = sz[e];
        sys[e] = y * (z / (1.f + __expf(-z)));
    }
    __syncthreads();

    float o = sx[tid];
    const float* wr = out_w + (size_t)tid * EDQ;
    for (int k = 0; k < 512; ++k) o += sys[k] * wr[k];
    g_xb[b * DQ + tid] = o;
}

// ---------------------------------------------------------------------------
// head: concat(xc[:, -1], xb) -> fc1 -> fc2
// ---------------------------------------------------------------------------
__global__ void __launch_bounds__(256) k_head(const float* __restrict__ fc_w,
                                              const float* __restrict__ fc_b,
                                              const float* __restrict__ fc2_w,
                                              const float* __restrict__ fc2_b,
                                              float* __restrict__ out) {
    __shared__ float sxl[512], sfc1[256];
    int b = blockIdx.x, tid = threadIdx.x;
    sxl[tid]       = g_xc[(size_t)(b * LQ + LQ - 1) * DQ + tid];
    sxl[256 + tid] = g_xb[b * DQ + tid];
    __syncthreads();
    float a = fc_b[tid];
    const float* wr = fc_w + (size_t)tid * (2 * DQ);
    for (int k = 0; k < 512; ++k) a += sxl[k] * wr[k];
    sfc1[tid] = a;
    __syncthreads();
    if (tid < 2) {
        float o = fc2_b[tid];
        const float* wr2 = fc2_w + tid * DQ;
        for (int k = 0; k < 256; ++k) o += sfc1[k] * wr2[k];
        out[b * 2 + tid] = o;
    }
}

// ---------------------------------------------------------------------------
// Host-side driver
// ---------------------------------------------------------------------------
static float* symf(const void* s) {
    void* p = nullptr;
    cudaGetSymbolAddress(&p, s);
    return (float*)p;
}

static void fwd_layer(float* x, const float* const* p, int l) {
    const float* norm_w = p[0] + (size_t)l * DQ;
    const float* in_w   = p[1] + (size_t)l * 2 * EDQ * DQ;
    const float* conv_w = p[2] + (size_t)l * EDQ * 4;
    const float* conv_b = p[3] + (size_t)l * EDQ;
    const float* xp_w   = p[4] + (size_t)l * (DTRQ + 2 * NSTQ) * EDQ;
    const float* dt_w   = p[5] + (size_t)l * EDQ * DTRQ;
    const float* dt_b   = p[6] + (size_t)l * EDQ;
    const float* A_log  = p[7] + (size_t)l * EDQ * NSTQ;
    const float* Dp     = p[8] + (size_t)l * EDQ;
    const float* out_w  = p[9] + (size_t)l * DQ * EDQ;

    const int T = NIMG;
    float* xn  = symf(g_xn);
    float* xz  = symf(g_xz);
    float* xcs = symf(g_xcs);
    float* dbc = symf(g_dbc);
    float* ys  = symf(g_ys);

    k_rms<<<T, 256>>>(x, norm_w, xn);
    k_gemm<<<dim3(16, 16), 256>>>(xn, DQ, in_w, DQ, xz, 1024, T, 1024, DQ, nullptr, 0);
    k_convsilu<<<(T * EDQ + 255) / 256, 256>>>(conv_w, conv_b, T, LQ);
    k_gemm<<<dim3(1, 16), 256>>>(xcs, EDQ, xp_w, EDQ, dbc, 48, T, 48, EDQ, nullptr, 0);
    k_scan_f<<<dim3(EDQ / 128, BQ), 128>>>(A_log, Dp, dt_w, dt_b, LQ);
    k_gemm<<<dim3(4, 16), 256>>>(ys, EDQ, out_w, EDQ, x, DQ, T, DQ, EDQ, nullptr, 1);
}

extern "C" void kernel_launch(void* const* d_in, const int* in_sizes, int n_in,
                              void* d_out, int out_size) {
    const float* video = (const float*)d_in[0];
    const float* audio = (const float*)d_in[1];
    const float* c1w = (const float*)d_in[2];
    const float* c1b = (const float*)d_in[3];
    const float* c2w = (const float*)d_in[4];
    const float* c2b = (const float*)d_in[5];
    const float* fcw = (const float*)d_in[6];
    const float* fcb = (const float*)d_in[7];
    const float* fwdp[10];
    const float* bwdp[10];
    for (int i = 0; i < 10; ++i) fwdp[i] = (const float*)d_in[8 + i];
    for (int i = 0; i < 10; ++i) bwdp[i] = (const float*)d_in[18 + i];
    const float* fc_w  = (const float*)d_in[28];
    const float* fc_b  = (const float*)d_in[29];
    const float* fc2_w = (const float*)d_in[30];
    const float* fc2_b = (const float*)d_in[31];
    float* out = (float*)d_out;

    cudaFuncSetAttribute(k_conv1_mma, cudaFuncAttributeMaxDynamicSharedMemorySize,
                         C1_SMEM_BYTES);
    cudaFuncSetAttribute(k_conv2_mma, cudaFuncAttributeMaxDynamicSharedMemorySize,
                         C2_SMEM_BYTES);

    // launch order: capture slot 4 = k_conv1_mma this round
    k_audio<<<(BQ * LQ * N_MFCC + 255) / 256, 256>>>(audio);          // 1
    k_filler<<<1, 32>>>();                                            // 2
    k_filler<<<1, 32>>>();                                            // 3
    k_conv1_mma<<<NIMG, 512, C1_SMEM_BYTES>>>(video, c1w, c1b);       // 4 (captured)
    k_conv2_mma<<<NIMG, 512, C2_SMEM_BYTES>>>(c2w, c2b);              // 5
    k_cnnfc<<<NIMG, 256>>>(fcw, fcb);                                 // 6
    k_lastcol<<<(BQ * DQ + 255) / 256, 256>>>();                      // 7

    float* xc = symf(g_xc);

    for (int l = 0; l < NLQ; ++l) fwd_layer(xc, fwdp, l);

    for (int l = 0; l < NLQ; ++l) {
        const float* p[9];
        p[0] = bwdp[0] + (size_t)l * DQ;
        p[1] = bwdp[1] + (size_t)l * 2 * EDQ * DQ;
        p[2] = bwdp[2] + (size_t)l * EDQ * 4;
        p[3] = bwdp[3] + (size_t)l * EDQ;
        p[4] = bwdp[4] + (size_t)l * (DTRQ + 2 * NSTQ) * EDQ;
        p[5] = bwdp[5] + (size_t)l * EDQ * DTRQ;
        p[6] = bwdp[6] + (size_t)l * EDQ;
        p[7] = bwdp[8] + (size_t)l * EDQ;       // D
        p[8] = bwdp[9] + (size_t)l * DQ * EDQ;  // out_w
        k_bwd_layer<<<BQ, 256>>>(p[0], p[1], p[2], p[3], p[4], p[5], p[6],
                                 p[7], p[8]);
    }

    k_head<<<BQ, 256>>>(fc_w, fc_b, fc2_w, fc2_b, out);
}

// round 5
// speedup vs baseline: 1.0438x; 1.0078x over previous
#include <cuda_runtime.h>
#include <cuda_fp16.h>
#include <math.h>
#include <stdint.h>

// ---------------------------------------------------------------------------
// Problem constants
// ---------------------------------------------------------------------------
#define BQ      8
#define LQ      128
#define NIMG    1024          // BQ * LQ
#define DQ      256           // VID_FEAT + N_MFCC
#define EDQ     512           // 2*DQ
#define NSTQ    16
#define DTRQ    16
#define NLQ     4
#define VID_FEAT 196
#define N_MFCC   60

// ---------------------------------------------------------------------------
// Scratch (device globals; allocation-free per harness rules)
// ---------------------------------------------------------------------------
__device__ __half g_pool1[(size_t)NIMG * 32 * 1024];     // conv1+pool out (half)
__device__ float g_feat [NIMG * 64];                     // conv2+pool+mean out
__device__ float g_xc   [NIMG * DQ];                     // concat feats / fwd stream
__device__ float g_xn   [NIMG * DQ];                     // rmsnorm out
__device__ float g_xz   [NIMG * 2 * EDQ];                // in_proj out (x | z)
__device__ float g_xcs  [NIMG * EDQ];                    // conv+silu out
__device__ float g_dbc  [NIMG * 48];                     // x_proj out (dt|B|C)
__device__ float g_ys   [NIMG * EDQ];                    // scan out (gated)
__device__ float g_xb   [BQ * DQ];                       // bwd mamba stream
__device__ float g_fill [32];                            // filler target

// ---------------------------------------------------------------------------
// mma helpers
// ---------------------------------------------------------------------------
__device__ __forceinline__ void mma_tf32(float* c, float a0, float a1,
                                         float a2, float a3,
                                         float b0, float b1) {
    asm volatile(
        "mma.sync.aligned.m16n8k8.row.col.f32.tf32.tf32.f32 "
        "{%0,%1,%2,%3}, {%4,%5,%6,%7}, {%8,%9}, {%0,%1,%2,%3};"
        : "+f"(c[0]), "+f"(c[1]), "+f"(c[2]), "+f"(c[3])
        : "r"(__float_as_uint(a0)), "r"(__float_as_uint(a1)),
          "r"(__float_as_uint(a2)), "r"(__float_as_uint(a3)),
          "r"(__float_as_uint(b0)), "r"(__float_as_uint(b1)));
}

__device__ __forceinline__ void mma_fp16(float* c, uint32_t a0, uint32_t a1,
                                         uint32_t a2, uint32_t a3,
                                         uint32_t b0, uint32_t b1) {
    asm volatile(
        "mma.sync.aligned.m16n8k16.row.col.f32.f16.f16.f32 "
        "{%0,%1,%2,%3}, {%4,%5,%6,%7}, {%8,%9}, {%0,%1,%2,%3};"
        : "+f"(c[0]), "+f"(c[1]), "+f"(c[2]), "+f"(c[3])
        : "r"(a0), "r"(a1), "r"(a2), "r"(a3), "r"(b0), "r"(b1));
}

__device__ __forceinline__ float to_tf32(float v) {
    uint32_t u;
    asm("cvt.rna.tf32.f32 %0, %1;" : "=r"(u) : "f"(v));
    return __uint_as_float(u);
}

// ---------------------------------------------------------------------------
// conv1 via tf32 mma implicit GEMM + bias + relu + maxpool2, half pooled store
// ---------------------------------------------------------------------------
#define C1_SMEM_FLOATS (12288 + 32 * 40 + 32)
#define C1_SMEM_BYTES  (C1_SMEM_FLOATS * 4)

__global__ void __launch_bounds__(512) k_conv1_mma(const float* __restrict__ video,
                                                   const float* __restrict__ w,
                                                   const float* __restrict__ bias) {
    extern __shared__ float sm[];
    float* Xs = sm;                  // 12288
    float* Ws = Xs + 12288;          // 32*40
    float* sb = Ws + 32 * 40;        // 32
    int n = blockIdx.x;
    int tid = threadIdx.x;

    const float* img = video + (size_t)n * 12288;
    for (int i = tid; i < 12288; i += 512) Xs[i] = to_tf32(img[i]);
    for (int i = tid; i < 1280;  i += 512) Ws[i] = 0.f;
    if (tid < 32) sb[tid] = bias[tid];
    __syncthreads();
    for (int i = tid; i < 864; i += 512) {
        int oc = i / 27, r = i % 27;
        Ws[r * 40 + oc] = to_tf32(w[i]);
    }
    __syncthreads();

    int lane = tid & 31, wp = tid >> 5;
    int g = lane >> 2, l4 = lane & 3;
    int xh = wp & 3, yp = wp >> 2;
    int x0 = xh * 16;

    int ky0[4], kx0[4], ic0[4];
    int ky1[4], kx1[4], ic1[4];
#pragma unroll
    for (int kk = 0; kk < 4; ++kk) {
        int k0 = kk * 8 + l4;
        int k1 = k0 + 4;
        if (k0 < 27) { ic0[kk] = (k0 / 9) * 4096; int t = k0 % 9; ky0[kk] = t / 3; kx0[kk] = t % 3; }
        else         { ic0[kk] = 0; ky0[kk] = 1; kx0[kk] = 1; }
        if (k1 < 27) { ic1[kk] = (k1 / 9) * 4096; int t = k1 % 9; ky1[kk] = t / 3; kx1[kk] = t % 3; }
        else         { ic1[kk] = 0; ky1[kk] = 1; kx1[kk] = 1; }
    }

    for (int chunk = 0; chunk < 8; ++chunk) {
        int y = chunk * 8 + yp * 2;
        float acc[2][4][4];
#pragma unroll
        for (int t = 0; t < 2; ++t)
#pragma unroll
            for (int j = 0; j < 4; ++j)
#pragma unroll
                for (int i = 0; i < 4; ++i) acc[t][j][i] = 0.f;

#pragma unroll
        for (int kk = 0; kk < 4; ++kk) {
            int yA0 = y + ky0[kk] - 1,  yA1 = y + ky1[kk] - 1;
            int xgA = x0 + g + kx0[kk] - 1;
            int xgB = x0 + g + kx1[kk] - 1;
            bool pA0 = (unsigned)xgA < 64u, pA1 = (unsigned)(xgA + 8) < 64u;
            bool pB0 = (unsigned)xgB < 64u, pB1 = (unsigned)(xgB + 8) < 64u;
            bool y00 = (unsigned)yA0 < 64u, y01 = (unsigned)(yA0 + 1) < 64u;
            bool y10 = (unsigned)yA1 < 64u, y11 = (unsigned)(yA1 + 1) < 64u;
            const float* xb0 = Xs + ic0[kk] + yA0 * 64;
            const float* xb1 = Xs + ic1[kk] + yA1 * 64;
            float a0 = (y00 && pA0) ? xb0[xgA]          : 0.f;
            float a1 = (y00 && pA1) ? xb0[xgA + 8]      : 0.f;
            float a2 = (y10 && pB0) ? xb1[xgB]          : 0.f;
            float a3 = (y10 && pB1) ? xb1[xgB + 8]      : 0.f;
            float e0 = (y01 && pA0) ? xb0[64 + xgA]     : 0.f;
            float e1 = (y01 && pA1) ? xb0[64 + xgA + 8] : 0.f;
            float e2 = (y11 && pB0) ? xb1[64 + xgB]     : 0.f;
            float e3 = (y11 && pB1) ? xb1[64 + xgB + 8] : 0.f;
            const float* w0 = Ws + (kk * 8 + l4) * 40 + g;
            const float* w1 = w0 + 4 * 40;
#pragma unroll
            for (int j = 0; j < 4; ++j) {
                float b0 = w0[8 * j];
                float b1 = w1[8 * j];
                mma_tf32(acc[0][j], a0, a1, a2, a3, b0, b1);
                mma_tf32(acc[1][j], e0, e1, e2, e3, b0, b1);
            }
        }

        int py = chunk * 4 + yp;
#pragma unroll
        for (int j = 0; j < 4; ++j)
#pragma unroll
            for (int i = 0; i < 4; ++i) {
                float m = fmaxf(acc[0][j][i], acc[1][j][i]);
                m = fmaxf(m, __shfl_xor_sync(0xffffffffu, m, 4));
                int oc = 8 * j + 2 * l4 + (i & 1);
                m = fmaxf(m + sb[oc], 0.f);
                if ((g & 1) == 0) {
                    int px = ((x0 + g) >> 1) + ((i >= 2) ? 4 : 0);
                    g_pool1[(((size_t)n * 32 + oc) << 10) + (py << 5) + px] =
                        __float2half(m);
                }
            }
    }
}

// ---------------------------------------------------------------------------
// conv2 via fp16 m16n8k16 implicit GEMM + relu + maxpool2 + mean
// Xs half[1024 pos][36] (stride 36 half = conflict-free), Ws half[64 oc][292]
// smem 113,408 B -> 2 blocks/SM (16 warps/SM)
// ---------------------------------------------------------------------------
#define C2_SMEM_BYTES (73728 + 37376 + 256 + 2048)

__global__ void __launch_bounds__(256, 2) k_conv2_mma(const float* __restrict__ w,
                                                      const float* __restrict__ bias) {
    extern __shared__ float smf[];
    __half* Xs = (__half*)smf;                             // 73728 B
    __half* Ws = (__half*)((char*)smf + 73728);            // 37376 B
    float* sb  = (float*)((char*)smf + 73728 + 37376);     // 256 B
    float* red = sb + 64;                                  // 2048 B
    const uint32_t* XsU = (const uint32_t*)Xs;
    const uint32_t* WsU = (const uint32_t*)Ws;
    int n = blockIdx.x, tid = threadIdx.x;

    const __half* src = g_pool1 + (size_t)n * 32768;
    for (int i = tid; i < 32768; i += 256) {
        int ic = i >> 10, s = i & 1023;
        Xs[s * 36 + ic] = src[i];
    }
    for (int i = tid; i < 18432; i += 256) {
        int oc = i / 288, r = i % 288;
        int ic = r / 9, t = r % 9;
        Ws[oc * 292 + t * 32 + ic] = __float2half(w[i]);
    }
    if (tid < 64) sb[tid] = bias[tid];
    __syncthreads();

    int lane = tid & 31, wp = tid >> 5;
    int g = lane >> 2, l4 = lane & 3;
    int ypair = wp >> 1, xh = wp & 1;
    int x0 = xh * 16;

    float cs[8][2];
#pragma unroll
    for (int j = 0; j < 8; ++j) { cs[j][0] = 0.f; cs[j][1] = 0.f; }

    for (int c = 0; c < 4; ++c) {
        int y = c * 8 + ypair * 2;
        float acc[2][8][4];
#pragma unroll
        for (int t = 0; t < 2; ++t)
#pragma unroll
            for (int j = 0; j < 8; ++j)
#pragma unroll
                for (int i = 0; i < 4; ++i) acc[t][j][i] = 0.f;

#pragma unroll
        for (int ky = 0; ky < 3; ++ky) {
            int yA = y + ky - 1;
            int yB = yA + 1;
            bool yokA = (unsigned)yA < 32u;
            bool yokB = (unsigned)yB < 32u;
#pragma unroll
            for (int kx = 0; kx < 3; ++kx) {
                int xg = x0 + g + kx - 1;
                bool p0 = (unsigned)xg < 32u;
                bool p1 = (unsigned)(xg + 8) < 32u;
                int posA = yA * 32 + xg;
                int posB = posA + 32;
#pragma unroll
                for (int icg2 = 0; icg2 < 16; icg2 += 8) {   // ic-group/2
                    int ib = icg2 + l4;
                    uint32_t a0 = (yokA && p0) ? XsU[posA * 18 + ib]           : 0u;
                    uint32_t a1 = (yokA && p1) ? XsU[(posA + 8) * 18 + ib]     : 0u;
                    uint32_t a2 = (yokA && p0) ? XsU[posA * 18 + ib + 4]       : 0u;
                    uint32_t a3 = (yokA && p1) ? XsU[(posA + 8) * 18 + ib + 4] : 0u;
                    uint32_t e0 = (yokB && p0) ? XsU[posB * 18 + ib]           : 0u;
                    uint32_t e1 = (yokB && p1) ? XsU[(posB + 8) * 18 + ib]     : 0u;
                    uint32_t e2 = (yokB && p0) ? XsU[posB * 18 + ib + 4]       : 0u;
                    uint32_t e3 = (yokB && p1) ? XsU[(posB + 8) * 18 + ib + 4] : 0u;
                    int kb = (ky * 3 + kx) * 16 + ib;
#pragma unroll
                    for (int j = 0; j < 8; ++j) {
                        uint32_t b0 = WsU[(j * 8 + g) * 146 + kb];
                        uint32_t b1 = WsU[(j * 8 + g) * 146 + kb + 4];
                        mma_fp16(acc[0][j], a0, a1, a2, a3, b0, b1);
                        mma_fp16(acc[1][j], e0, e1, e2, e3, b0, b1);
                    }
                }
            }
        }
#pragma unroll
        for (int j = 0; j < 8; ++j)
#pragma unroll
            for (int i = 0; i < 4; ++i) {
                float m = fmaxf(acc[0][j][i], acc[1][j][i]);
                m = fmaxf(m, __shfl_xor_sync(0xffffffffu, m, 4));
                m = fmaxf(m + sb[8 * j + 2 * l4 + (i & 1)], 0.f);
                cs[j][i & 1] += m;
            }
    }

#pragma unroll
    for (int j = 0; j < 8; ++j)
#pragma unroll
        for (int i = 0; i < 2; ++i) {
            float v = cs[j][i];
            v += __shfl_xor_sync(0xffffffffu, v, 16);
            v += __shfl_xor_sync(0xffffffffu, v, 8);
            v += __shfl_xor_sync(0xffffffffu, v, 4);
            cs[j][i] = v;
        }
    if (g == 0) {
#pragma unroll
        for (int j = 0; j < 8; ++j) {
            red[wp * 64 + 8 * j + 2 * l4]     = cs[j][0];
            red[wp * 64 + 8 * j + 2 * l4 + 1] = cs[j][1];
        }
    }
    __syncthreads();
    if (tid < 64) {
        float s = 0.f;
#pragma unroll
        for (int ww = 0; ww < 8; ++ww) s += red[ww * 64 + tid];
        g_feat[n * 64 + tid] = s * (1.0f / 512.0f);
    }
}

// ---------------------------------------------------------------------------
// small kernels
// ---------------------------------------------------------------------------
__global__ void __launch_bounds__(256) k_cnnfc(const float* __restrict__ fw,
                                               const float* __restrict__ fb) {
    __shared__ float sf[64];
    int n = blockIdx.x;
    if (threadIdx.x < 64) sf[threadIdx.x] = g_feat[n * 64 + threadIdx.x];
    __syncthreads();
    int j = threadIdx.x;
    if (j < VID_FEAT) {
        float acc = fb[j];
        const float* wr = fw + j * 64;
#pragma unroll
        for (int k = 0; k < 64; ++k) acc += sf[k] * wr[k];
        g_xc[(size_t)n * DQ + j] = acc;
    }
}

__global__ void k_audio(const float* __restrict__ a) {
    int i = blockIdx.x * 256 + threadIdx.x;
    if (i >= BQ * LQ * N_MFCC) return;
    int m = i % N_MFCC;
    int t = i / N_MFCC;
    g_xc[(size_t)t * DQ + VID_FEAT + m] = a[i];
}

__global__ void k_lastcol() {
    int i = blockIdx.x * 256 + threadIdx.x;
    if (i < BQ * DQ) {
        int b = i >> 8, d = i & 255;
        g_xb[i] = g_xc[(size_t)(b * LQ + LQ - 1) * DQ + d];
    }
}

// ---------------------------------------------------------------------------
// RMSNorm over D=256, one block per token
// ---------------------------------------------------------------------------
__global__ void __launch_bounds__(256) k_rms(const float* __restrict__ x,
                                             const float* __restrict__ w,
                                             float* __restrict__ out) {
    int t = blockIdx.x;
    float v = x[(size_t)t * DQ + threadIdx.x];
    float s = v * v;
#pragma unroll
    for (int off = 16; off > 0; off >>= 1) s += __shfl_xor_sync(~0u, s, off);
    __shared__ float red[8];
    if ((threadIdx.x & 31) == 0) red[threadIdx.x >> 5] = s;
    __syncthreads();
    float tot = red[0] + red[1] + red[2] + red[3] +
                red[4] + red[5] + red[6] + red[7];
    float inv = rsqrtf(tot * (1.0f / DQ) + 1e-5f);
    out[(size_t)t * DQ + threadIdx.x] = v * inv * w[threadIdx.x];
}

// ---------------------------------------------------------------------------
// generic SGEMM: C[M,N] = A[M,K] @ B[N,K]^T (+bias) (+=C if accum)
// ---------------------------------------------------------------------------
__global__ void __launch_bounds__(256) k_gemm(const float* __restrict__ A, int lda,
                                              const float* __restrict__ Bw, int ldb,
                                              float* __restrict__ C, int ldc,
                                              int M, int N, int K,
                                              const float* __restrict__ bias,
                                              int accum) {
    __shared__ float As[16][68];
    __shared__ float Bs[16][68];
    int m0 = blockIdx.y * 64, n0 = blockIdx.x * 64;
    int ty = threadIdx.x >> 4, tx = threadIdx.x & 15;
    float acc[4][4] = {};
    for (int k0 = 0; k0 < K; k0 += 16) {
        for (int i = threadIdx.x; i < 1024; i += 256) {
            int r = i >> 4, kk = i & 15;
            int gk = k0 + kk;
            As[kk][r] = (m0 + r < M && gk < K) ? A[(size_t)(m0 + r) * lda + gk] : 0.f;
            Bs[kk][r] = (n0 + r < N && gk < K) ? Bw[(size_t)(n0 + r) * ldb + gk] : 0.f;
        }
        __syncthreads();
#pragma unroll
        for (int kk = 0; kk < 16; ++kk) {
            float4 av = *reinterpret_cast<const float4*>(&As[kk][ty * 4]);
            float4 bv = *reinterpret_cast<const float4*>(&Bs[kk][tx * 4]);
            float a[4] = {av.x, av.y, av.z, av.w};
            float b[4] = {bv.x, bv.y, bv.z, bv.w};
#pragma unroll
            for (int i = 0; i < 4; ++i)
#pragma unroll
                for (int j = 0; j < 4; ++j) acc[i][j] += a[i] * b[j];
        }
        __syncthreads();
    }
#pragma unroll
    for (int i = 0; i < 4; ++i) {
        int r = m0 + ty * 4 + i;
        if (r >= M) continue;
#pragma unroll
        for (int j = 0; j < 4; ++j) {
            int c = n0 + tx * 4 + j;
            if (c >= N) continue;
            float v = acc[i][j];
            if (bias) v += bias[c];
            if (accum) v += C[(size_t)r * ldc + c];
            C[(size_t)r * ldc + c] = v;
        }
    }
}

// ---------------------------------------------------------------------------
// causal depthwise conv4 + silu
// ---------------------------------------------------------------------------
__global__ void k_convsilu(const float* __restrict__ cw,
                           const float* __restrict__ cb, int T, int Lc) {
    int i = blockIdx.x * 256 + threadIdx.x;
    if (i >= T * EDQ) return;
    int t = i >> 9, e = i & 511;
    int l = t % Lc;
    float acc = cb[e];
#pragma unroll
    for (int k = 0; k < 4; ++k) {
        int li = l + k - 3;
        if (li >= 0) acc += g_xz[(size_t)(t + k - 3) * 1024 + e] * cw[e * 4 + k];
    }
    acc = acc / (1.f + __expf(-acc));
    g_xcs[i] = acc;
}

// ---------------------------------------------------------------------------
// fused scan: dt-proj + softplus + selective scan + D*x + silu(z) gate
// 2 threads per (b,e) channel: 8 states each, shfl-combine y
// ---------------------------------------------------------------------------
__global__ void __launch_bounds__(256) k_scan_f(const float* __restrict__ A_log,
                                                const float* __restrict__ Dp,
                                                const float* __restrict__ dt_w,
                                                const float* __restrict__ dt_b,
                                                int Lc) {
    int tid = threadIdx.x;
    int e  = blockIdx.x * 128 + (tid >> 1);
    int nh = tid & 1;
    int b  = blockIdx.y;
    float negA[8], dtw[DTRQ], h[8];
#pragma unroll
    for (int n = 0; n < 8; ++n) negA[n] = -__expf(A_log[e * NSTQ + nh * 8 + n]);
#pragma unroll
    for (int n = 0; n < DTRQ; ++n) dtw[n] = dt_w[e * DTRQ + n];
    float dtb = dt_b[e];
    float Dv = Dp[e];
#pragma unroll
    for (int n = 0; n < 8; ++n) h[n] = 0.f;
    for (int t = 0; t < Lc; ++t) {
        size_t idx = (size_t)(b * Lc + t);
        const float* bc = g_dbc + idx * 48;
        float draw = dtb;
#pragma unroll
        for (int n = 0; n < DTRQ; ++n) draw += __ldg(bc + n) * dtw[n];
        float dlt = (draw > 20.f) ? draw : log1pf(__expf(draw));
        float xv = g_xcs[idx * EDQ + e];
        float z  = g_xz[idx * 1024 + EDQ + e];
        float dx = dlt * xv;
        float y = 0.f;
#pragma unroll
        for (int n = 0; n < 8; ++n) {
            float hn = __expf(dlt * negA[n]) * h[n] + dx * __ldg(bc + 16 + nh * 8 + n);
            h[n] = hn;
            y += hn * __ldg(bc + 32 + nh * 8 + n);
        }
        y += __shfl_xor_sync(0xffffffffu, y, 1);
        if (nh == 0) {
            float sz = z / (1.f + __expf(-z));
            g_ys[idx * EDQ + e] = (y + Dv * xv) * sz;
        }
    }
}

// ---------------------------------------------------------------------------
// whole backward Mamba layer (T=1 per batch): one block per batch element
// ---------------------------------------------------------------------------
__global__ void __launch_bounds__(256) k_bwd_layer(
    const float* __restrict__ norm_w, const float* __restrict__ in_w,
    const float* __restrict__ conv_w, const float* __restrict__ conv_b,
    const float* __restrict__ xp_w,  const float* __restrict__ dt_w,
    const float* __restrict__ dt_b,  const float* __restrict__ Dp,
    const float* __restrict__ out_w) {
    __shared__ float sx[256], sxn[256], sxcs[512], sz[512], sdbc[48], sys[512];
    __shared__ float sred[8];
    __shared__ float sbc;
    int b = blockIdx.x, tid = threadIdx.x;
    int lane = tid & 31, wp = tid >> 5;

    float xv = g_xb[b * DQ + tid];
    sx[tid] = xv;
    float s = xv * xv;
#pragma unroll
    for (int off = 16; off > 0; off >>= 1) s += __shfl_xor_sync(~0u, s, off);
    if (lane == 0) sred[wp] = s;
    __syncthreads();
    float tot = sred[0] + sred[1] + sred[2] + sred[3] +
                sred[4] + sred[5] + sred[6] + sred[7];
    float inv = rsqrtf(tot * (1.0f / DQ) + 1e-5f);
    sxn[tid] = xv * inv * norm_w[tid];
    __syncthreads();

    for (int q = 0; q < 4; ++q) {
        int o = q * 256 + tid;
        float acc = 0.f;
        const float* wr = in_w + (size_t)o * DQ;
        for (int k = 0; k < 256; ++k) acc += sxn[k] * wr[k];
        if (o < EDQ) {
            float v = acc * conv_w[o * 4 + 3] + conv_b[o];
            sxcs[o] = v / (1.f + __expf(-v));
        } else {
            sz[o - EDQ] = acc;
        }
    }
    __syncthreads();

    for (int rr = 0; rr < 6; ++rr) {
        int r = wp * 6 + rr;
        float a = 0.f;
        const float* wr = xp_w + (size_t)r * EDQ;
        for (int k = lane; k < 512; k += 32) a += sxcs[k] * wr[k];
#pragma unroll
        for (int off = 16; off > 0; off >>= 1) a += __shfl_xor_sync(~0u, a, off);
        if (lane == 0) sdbc[r] = a;
    }
    __syncthreads();
    if (tid == 0) {
        float a = 0.f;
#pragma unroll
        for (int n = 0; n < NSTQ; ++n) a += sdbc[16 + n] * sdbc[32 + n];
        sbc = a;
    }
    __syncthreads();

    for (int q = 0; q < 2; ++q) {
        int e = q * 256 + tid;
        float d = dt_b[e];
        const float* wr = dt_w + e * DTRQ;
#pragma unroll
        for (int n = 0; n < DTRQ; ++n) d += sdbc[n] * wr[n];
        d = (d > 20.f) ? d : log1pf(__expf(d));
        float xc_ = sxcs[e];
        float y = d * xc_ * sbc + Dp[e] * xc_;
        float z = sz[e];
        sys[e] = y * (z / (1.f + __expf(-z)));
    }
    __syncthreads();

    float o = sx[tid];
    const float* wr = out_w + (size_t)tid * EDQ;
    for (int k = 0; k < 512; ++k) o += sys[k] * wr[k];
    g_xb[b * DQ + tid] = o;
}

// ---------------------------------------------------------------------------
// head: concat(xc[:, -1], xb) -> fc1 -> fc2
// ---------------------------------------------------------------------------
__global__ void __launch_bounds__(256) k_head(const float* __restrict__ fc_w,
                                              const float* __restrict__ fc_b,
                                              const float* __restrict__ fc2_w,
                                              const float* __restrict__ fc2_b,
                                              float* __restrict__ out) {
    __shared__ float sxl[512], sfc1[256];
    int b = blockIdx.x, tid = threadIdx.x;
    sxl[tid]       = g_xc[(size_t)(b * LQ + LQ - 1) * DQ + tid];
    sxl[256 + tid] = g_xb[b * DQ + tid];
    __syncthreads();
    float a = fc_b[tid];
    const float* wr = fc_w + (size_t)tid * (2 * DQ);
    for (int k = 0; k < 512; ++k) a += sxl[k] * wr[k];
    sfc1[tid] = a;
    __syncthreads();
    if (tid < 2) {
        float o = fc2_b[tid];
        const float* wr2 = fc2_w + tid * DQ;
        for (int k = 0; k < 256; ++k) o += sfc1[k] * wr2[k];
        out[b * 2 + tid] = o;
    }
}

// ---------------------------------------------------------------------------
// Host-side driver
// ---------------------------------------------------------------------------
static float* symf(const void* s) {
    void* p = nullptr;
    cudaGetSymbolAddress(&p, s);
    return (float*)p;
}

static void fwd_layer(float* x, const float* const* p, int l) {
    const float* norm_w = p[0] + (size_t)l * DQ;
    const float* in_w   = p[1] + (size_t)l * 2 * EDQ * DQ;
    const float* conv_w = p[2] + (size_t)l * EDQ * 4;
    const float* conv_b = p[3] + (size_t)l * EDQ;
    const float* xp_w   = p[4] + (size_t)l * (DTRQ + 2 * NSTQ) * EDQ;
    const float* dt_w   = p[5] + (size_t)l * EDQ * DTRQ;
    const float* dt_b   = p[6] + (size_t)l * EDQ;
    const float* A_log  = p[7] + (size_t)l * EDQ * NSTQ;
    const float* Dp     = p[8] + (size_t)l * EDQ;
    const float* out_w  = p[9] + (size_t)l * DQ * EDQ;

    const int T = NIMG;
    float* xn  = symf(g_xn);
    float* xz  = symf(g_xz);
    float* xcs = symf(g_xcs);
    float* dbc = symf(g_dbc);
    float* ys  = symf(g_ys);

    k_rms<<<T, 256>>>(x, norm_w, xn);
    k_gemm<<<dim3(16, 16), 256>>>(xn, DQ, in_w, DQ, xz, 1024, T, 1024, DQ, nullptr, 0);
    k_convsilu<<<(T * EDQ + 255) / 256, 256>>>(conv_w, conv_b, T, LQ);
    k_gemm<<<dim3(1, 16), 256>>>(xcs, EDQ, xp_w, EDQ, dbc, 48, T, 48, EDQ, nullptr, 0);
    k_scan_f<<<dim3(4, BQ), 256>>>(A_log, Dp, dt_w, dt_b, LQ);
    k_gemm<<<dim3(4, 16), 256>>>(ys, EDQ, out_w, EDQ, x, DQ, T, DQ, EDQ, nullptr, 1);
}

extern "C" void kernel_launch(void* const* d_in, const int* in_sizes, int n_in,
                              void* d_out, int out_size) {
    const float* video = (const float*)d_in[0];
    const float* audio = (const float*)d_in[1];
    const float* c1w = (const float*)d_in[2];
    const float* c1b = (const float*)d_in[3];
    const float* c2w = (const float*)d_in[4];
    const float* c2b = (const float*)d_in[5];
    const float* fcw = (const float*)d_in[6];
    const float* fcb = (const float*)d_in[7];
    const float* fwdp[10];
    const float* bwdp[10];
    for (int i = 0; i < 10; ++i) fwdp[i] = (const float*)d_in[8 + i];
    for (int i = 0; i < 10; ++i) bwdp[i] = (const float*)d_in[18 + i];
    const float* fc_w  = (const float*)d_in[28];
    const float* fc_b  = (const float*)d_in[29];
    const float* fc2_w = (const float*)d_in[30];
    const float* fc2_b = (const float*)d_in[31];
    float* out = (float*)d_out;

    cudaFuncSetAttribute(k_conv1_mma, cudaFuncAttributeMaxDynamicSharedMemorySize,
                         C1_SMEM_BYTES);
    cudaFuncSetAttribute(k_conv2_mma, cudaFuncAttributeMaxDynamicSharedMemorySize,
                         C2_SMEM_BYTES);

    // capture slot 4 = dummy k_scan_f (real shapes; g_ys overwritten later)
    k_audio<<<(BQ * LQ * N_MFCC + 255) / 256, 256>>>(audio);              // 1
    k_conv1_mma<<<NIMG, 512, C1_SMEM_BYTES>>>(video, c1w, c1b);           // 2
    k_conv2_mma<<<NIMG, 256, C2_SMEM_BYTES>>>(c2w, c2b);                  // 3
    k_scan_f<<<dim3(4, BQ), 256>>>(fwdp[7], fwdp[8], fwdp[5], fwdp[6], LQ); // 4 (captured)
    k_cnnfc<<<NIMG, 256>>>(fcw, fcb);                                     // 5
    k_lastcol<<<(BQ * DQ + 255) / 256, 256>>>();                          // 6

    float* xc = symf(g_xc);

    for (int l = 0; l < NLQ; ++l) fwd_layer(xc, fwdp, l);

    for (int l = 0; l < NLQ; ++l) {
        const float* p[9];
        p[0] = bwdp[0] + (size_t)l * DQ;
        p[1] = bwdp[1] + (size_t)l * 2 * EDQ * DQ;
        p[2] = bwdp[2] + (size_t)l * EDQ * 4;
        p[3] = bwdp[3] + (size_t)l * EDQ;
        p[4] = bwdp[4] + (size_t)l * (DTRQ + 2 * NSTQ) * EDQ;
        p[5] = bwdp[5] + (size_t)l * EDQ * DTRQ;
        p[6] = bwdp[6] + (size_t)l * EDQ;
        p[7] = bwdp[8] + (size_t)l * EDQ;       // D
        p[8] = bwdp[9] + (size_t)l * DQ * EDQ;  // out_w
        k_bwd_layer<<<BQ, 256>>>(p[0], p[1], p[2], p[3], p[4], p[5], p[6],
                                 p[7], p[8]);
    }

    k_head<<<BQ, 256>>>(fc_w, fc_b, fc2_w, fc2_b, out);
}

// round 6
// speedup vs baseline: 1.2438x; 1.1917x over previous
#include <cuda_runtime.h>
#include <cuda_fp16.h>
#include <math.h>
#include <stdint.h>

// ---------------------------------------------------------------------------
// Problem constants
// ---------------------------------------------------------------------------
#define BQ      8
#define LQ      128
#define NIMG    1024          // BQ * LQ
#define DQ      256           // VID_FEAT + N_MFCC
#define EDQ     512           // 2*DQ
#define NSTQ    16
#define DTRQ    16
#define NLQ     4
#define VID_FEAT 196
#define N_MFCC   60

// ---------------------------------------------------------------------------
// Scratch (device globals; allocation-free per harness rules)
// ---------------------------------------------------------------------------
__device__ __half g_pool1[(size_t)NIMG * 32 * 1024];     // conv1+pool out (half)
__device__ float g_feat [NIMG * 64];                     // conv2+pool+mean out
__device__ float g_xc   [NIMG * DQ];                     // concat feats / fwd stream
__device__ float g_xn   [NIMG * DQ];                     // rmsnorm out
__device__ float g_xz   [NIMG * 2 * EDQ];                // in_proj out (x | z)
__device__ float g_xcs  [NIMG * EDQ];                    // conv+silu out
__device__ float g_dbc  [NIMG * 48];                     // x_proj out (dt|B|C)
__device__ float g_ys   [NIMG * EDQ];                    // scan out (gated)
__device__ float g_xb   [BQ * DQ];                       // bwd mamba stream
__device__ float g_fill [32];                            // filler target

// ---------------------------------------------------------------------------
// mma helpers
// ---------------------------------------------------------------------------
__device__ __forceinline__ void mma_tf32(float* c, float a0, float a1,
                                         float a2, float a3,
                                         float b0, float b1) {
    asm volatile(
        "mma.sync.aligned.m16n8k8.row.col.f32.tf32.tf32.f32 "
        "{%0,%1,%2,%3}, {%4,%5,%6,%7}, {%8,%9}, {%0,%1,%2,%3};"
        : "+f"(c[0]), "+f"(c[1]), "+f"(c[2]), "+f"(c[3])
        : "r"(__float_as_uint(a0)), "r"(__float_as_uint(a1)),
          "r"(__float_as_uint(a2)), "r"(__float_as_uint(a3)),
          "r"(__float_as_uint(b0)), "r"(__float_as_uint(b1)));
}

__device__ __forceinline__ void mma_fp16(float* c, uint32_t a0, uint32_t a1,
                                         uint32_t a2, uint32_t a3,
                                         uint32_t b0, uint32_t b1) {
    asm volatile(
        "mma.sync.aligned.m16n8k16.row.col.f32.f16.f16.f32 "
        "{%0,%1,%2,%3}, {%4,%5,%6,%7}, {%8,%9}, {%0,%1,%2,%3};"
        : "+f"(c[0]), "+f"(c[1]), "+f"(c[2]), "+f"(c[3])
        : "r"(a0), "r"(a1), "r"(a2), "r"(a3), "r"(b0), "r"(b1));
}

__device__ __forceinline__ float to_tf32(float v) {
    uint32_t u;
    asm("cvt.rna.tf32.f32 %0, %1;" : "=r"(u) : "f"(v));
    return __uint_as_float(u);
}

// ---------------------------------------------------------------------------
// conv1 via tf32 mma implicit GEMM + bias + relu + maxpool2, half pooled store
// ---------------------------------------------------------------------------
#define C1_SMEM_FLOATS (12288 + 32 * 40 + 32)
#define C1_SMEM_BYTES  (C1_SMEM_FLOATS * 4)

__global__ void __launch_bounds__(512) k_conv1_mma(const float* __restrict__ video,
                                                   const float* __restrict__ w,
                                                   const float* __restrict__ bias) {
    extern __shared__ float sm[];
    float* Xs = sm;                  // 12288
    float* Ws = Xs + 12288;          // 32*40
    float* sb = Ws + 32 * 40;        // 32
    int n = blockIdx.x;
    int tid = threadIdx.x;

    const float* img = video + (size_t)n * 12288;
    for (int i = tid; i < 12288; i += 512) Xs[i] = to_tf32(img[i]);
    for (int i = tid; i < 1280;  i += 512) Ws[i] = 0.f;
    if (tid < 32) sb[tid] = bias[tid];
    __syncthreads();
    for (int i = tid; i < 864; i += 512) {
        int oc = i / 27, r = i % 27;
        Ws[r * 40 + oc] = to_tf32(w[i]);
    }
    __syncthreads();

    int lane = tid & 31, wp = tid >> 5;
    int g = lane >> 2, l4 = lane & 3;
    int xh = wp & 3, yp = wp >> 2;
    int x0 = xh * 16;

    int ky0[4], kx0[4], ic0[4];
    int ky1[4], kx1[4], ic1[4];
#pragma unroll
    for (int kk = 0; kk < 4; ++kk) {
        int k0 = kk * 8 + l4;
        int k1 = k0 + 4;
        if (k0 < 27) { ic0[kk] = (k0 / 9) * 4096; int t = k0 % 9; ky0[kk] = t / 3; kx0[kk] = t % 3; }
        else         { ic0[kk] = 0; ky0[kk] = 1; kx0[kk] = 1; }
        if (k1 < 27) { ic1[kk] = (k1 / 9) * 4096; int t = k1 % 9; ky1[kk] = t / 3; kx1[kk] = t % 3; }
        else         { ic1[kk] = 0; ky1[kk] = 1; kx1[kk] = 1; }
    }

    for (int chunk = 0; chunk < 8; ++chunk) {
        int y = chunk * 8 + yp * 2;
        float acc[2][4][4];
#pragma unroll
        for (int t = 0; t < 2; ++t)
#pragma unroll
            for (int j = 0; j < 4; ++j)
#pragma unroll
                for (int i = 0; i < 4; ++i) acc[t][j][i] = 0.f;

#pragma unroll
        for (int kk = 0; kk < 4; ++kk) {
            int yA0 = y + ky0[kk] - 1,  yA1 = y + ky1[kk] - 1;
            int xgA = x0 + g + kx0[kk] - 1;
            int xgB = x0 + g + kx1[kk] - 1;
            bool pA0 = (unsigned)xgA < 64u, pA1 = (unsigned)(xgA + 8) < 64u;
            bool pB0 = (unsigned)xgB < 64u, pB1 = (unsigned)(xgB + 8) < 64u;
            bool y00 = (unsigned)yA0 < 64u, y01 = (unsigned)(yA0 + 1) < 64u;
            bool y10 = (unsigned)yA1 < 64u, y11 = (unsigned)(yA1 + 1) < 64u;
            const float* xb0 = Xs + ic0[kk] + yA0 * 64;
            const float* xb1 = Xs + ic1[kk] + yA1 * 64;
            float a0 = (y00 && pA0) ? xb0[xgA]          : 0.f;
            float a1 = (y00 && pA1) ? xb0[xgA + 8]      : 0.f;
            float a2 = (y10 && pB0) ? xb1[xgB]          : 0.f;
            float a3 = (y10 && pB1) ? xb1[xgB + 8]      : 0.f;
            float e0 = (y01 && pA0) ? xb0[64 + xgA]     : 0.f;
            float e1 = (y01 && pA1) ? xb0[64 + xgA + 8] : 0.f;
            float e2 = (y11 && pB0) ? xb1[64 + xgB]     : 0.f;
            float e3 = (y11 && pB1) ? xb1[64 + xgB + 8] : 0.f;
            const float* w0 = Ws + (kk * 8 + l4) * 40 + g;
            const float* w1 = w0 + 4 * 40;
#pragma unroll
            for (int j = 0; j < 4; ++j) {
                float b0 = w0[8 * j];
                float b1 = w1[8 * j];
                mma_tf32(acc[0][j], a0, a1, a2, a3, b0, b1);
                mma_tf32(acc[1][j], e0, e1, e2, e3, b0, b1);
            }
        }

        int py = chunk * 4 + yp;
#pragma unroll
        for (int j = 0; j < 4; ++j)
#pragma unroll
            for (int i = 0; i < 4; ++i) {
                float m = fmaxf(acc[0][j][i], acc[1][j][i]);
                m = fmaxf(m, __shfl_xor_sync(0xffffffffu, m, 4));
                int oc = 8 * j + 2 * l4 + (i & 1);
                m = fmaxf(m + sb[oc], 0.f);
                if ((g & 1) == 0) {
                    int px = ((x0 + g) >> 1) + ((i >= 2) ? 4 : 0);
                    g_pool1[(((size_t)n * 32 + oc) << 10) + (py << 5) + px] =
                        __float2half(m);
                }
            }
    }
}

// ---------------------------------------------------------------------------
// conv2 via fp16 m16n8k16 implicit GEMM + relu + maxpool2 + mean
// ---------------------------------------------------------------------------
#define C2_SMEM_BYTES (73728 + 37376 + 256 + 2048)

__global__ void __launch_bounds__(256, 2) k_conv2_mma(const float* __restrict__ w,
                                                      const float* __restrict__ bias) {
    extern __shared__ float smf[];
    __half* Xs = (__half*)smf;                             // 73728 B
    __half* Ws = (__half*)((char*)smf + 73728);            // 37376 B
    float* sb  = (float*)((char*)smf + 73728 + 37376);     // 256 B
    float* red = sb + 64;                                  // 2048 B
    const uint32_t* XsU = (const uint32_t*)Xs;
    const uint32_t* WsU = (const uint32_t*)Ws;
    int n = blockIdx.x, tid = threadIdx.x;

    const __half* src = g_pool1 + (size_t)n * 32768;
    for (int i = tid; i < 32768; i += 256) {
        int ic = i >> 10, s = i & 1023;
        Xs[s * 36 + ic] = src[i];
    }
    for (int i = tid; i < 18432; i += 256) {
        int oc = i / 288, r = i % 288;
        int ic = r / 9, t = r % 9;
        Ws[oc * 292 + t * 32 + ic] = __float2half(w[i]);
    }
    if (tid < 64) sb[tid] = bias[tid];
    __syncthreads();

    int lane = tid & 31, wp = tid >> 5;
    int g = lane >> 2, l4 = lane & 3;
    int ypair = wp >> 1, xh = wp & 1;
    int x0 = xh * 16;

    float cs[8][2];
#pragma unroll
    for (int j = 0; j < 8; ++j) { cs[j][0] = 0.f; cs[j][1] = 0.f; }

    for (int c = 0; c < 4; ++c) {
        int y = c * 8 + ypair * 2;
        float acc[2][8][4];
#pragma unroll
        for (int t = 0; t < 2; ++t)
#pragma unroll
            for (int j = 0; j < 8; ++j)
#pragma unroll
                for (int i = 0; i < 4; ++i) acc[t][j][i] = 0.f;

#pragma unroll
        for (int ky = 0; ky < 3; ++ky) {
            int yA = y + ky - 1;
            int yB = yA + 1;
            bool yokA = (unsigned)yA < 32u;
            bool yokB = (unsigned)yB < 32u;
#pragma unroll
            for (int kx = 0; kx < 3; ++kx) {
                int xg = x0 + g + kx - 1;
                bool p0 = (unsigned)xg < 32u;
                bool p1 = (unsigned)(xg + 8) < 32u;
                int posA = yA * 32 + xg;
                int posB = posA + 32;
#pragma unroll
                for (int icg2 = 0; icg2 < 16; icg2 += 8) {
                    int ib = icg2 + l4;
                    uint32_t a0 = (yokA && p0) ? XsU[posA * 18 + ib]           : 0u;
                    uint32_t a1 = (yokA && p1) ? XsU[(posA + 8) * 18 + ib]     : 0u;
                    uint32_t a2 = (yokA && p0) ? XsU[posA * 18 + ib + 4]       : 0u;
                    uint32_t a3 = (yokA && p1) ? XsU[(posA + 8) * 18 + ib + 4] : 0u;
                    uint32_t e0 = (yokB && p0) ? XsU[posB * 18 + ib]           : 0u;
                    uint32_t e1 = (yokB && p1) ? XsU[(posB + 8) * 18 + ib]     : 0u;
                    uint32_t e2 = (yokB && p0) ? XsU[posB * 18 + ib + 4]       : 0u;
                    uint32_t e3 = (yokB && p1) ? XsU[(posB + 8) * 18 + ib + 4] : 0u;
                    int kb = (ky * 3 + kx) * 16 + ib;
#pragma unroll
                    for (int j = 0; j < 8; ++j) {
                        uint32_t b0 = WsU[(j * 8 + g) * 146 + kb];
                        uint32_t b1 = WsU[(j * 8 + g) * 146 + kb + 4];
                        mma_fp16(acc[0][j], a0, a1, a2, a3, b0, b1);
                        mma_fp16(acc[1][j], e0, e1, e2, e3, b0, b1);
                    }
                }
            }
        }
#pragma unroll
        for (int j = 0; j < 8; ++j)
#pragma unroll
            for (int i = 0; i < 4; ++i) {
                float m = fmaxf(acc[0][j][i], acc[1][j][i]);
                m = fmaxf(m, __shfl_xor_sync(0xffffffffu, m, 4));
                m = fmaxf(m + sb[8 * j + 2 * l4 + (i & 1)], 0.f);
                cs[j][i & 1] += m;
            }
    }

#pragma unroll
    for (int j = 0; j < 8; ++j)
#pragma unroll
        for (int i = 0; i < 2; ++i) {
            float v = cs[j][i];
            v += __shfl_xor_sync(0xffffffffu, v, 16);
            v += __shfl_xor_sync(0xffffffffu, v, 8);
            v += __shfl_xor_sync(0xffffffffu, v, 4);
            cs[j][i] = v;
        }
    if (g == 0) {
#pragma unroll
        for (int j = 0; j < 8; ++j) {
            red[wp * 64 + 8 * j + 2 * l4]     = cs[j][0];
            red[wp * 64 + 8 * j + 2 * l4 + 1] = cs[j][1];
        }
    }
    __syncthreads();
    if (tid < 64) {
        float s = 0.f;
#pragma unroll
        for (int ww = 0; ww < 8; ++ww) s += red[ww * 64 + tid];
        g_feat[n * 64 + tid] = s * (1.0f / 512.0f);
    }
}

// ---------------------------------------------------------------------------
// small kernels
// ---------------------------------------------------------------------------
__global__ void k_filler() { if (threadIdx.x < 32) g_fill[threadIdx.x] = 0.f; }

__global__ void __launch_bounds__(256) k_cnnfc(const float* __restrict__ fw,
                                               const float* __restrict__ fb) {
    __shared__ float sf[64];
    int n = blockIdx.x;
    if (threadIdx.x < 64) sf[threadIdx.x] = g_feat[n * 64 + threadIdx.x];
    __syncthreads();
    int j = threadIdx.x;
    if (j < VID_FEAT) {
        float acc = fb[j];
        const float* wr = fw + j * 64;
#pragma unroll
        for (int k = 0; k < 64; ++k) acc += sf[k] * wr[k];
        g_xc[(size_t)n * DQ + j] = acc;
    }
}

__global__ void k_audio(const float* __restrict__ a) {
    int i = blockIdx.x * 256 + threadIdx.x;
    if (i >= BQ * LQ * N_MFCC) return;
    int m = i % N_MFCC;
    int t = i / N_MFCC;
    g_xc[(size_t)t * DQ + VID_FEAT + m] = a[i];
}

__global__ void k_lastcol() {
    int i = blockIdx.x * 256 + threadIdx.x;
    if (i < BQ * DQ) {
        int b = i >> 8, d = i & 255;
        g_xb[i] = g_xc[(size_t)(b * LQ + LQ - 1) * DQ + d];
    }
}

// ---------------------------------------------------------------------------
// RMSNorm over D=256, one block per token
// ---------------------------------------------------------------------------
__global__ void __launch_bounds__(256) k_rms(const float* __restrict__ x,
                                             const float* __restrict__ w,
                                             float* __restrict__ out) {
    int t = blockIdx.x;
    float v = x[(size_t)t * DQ + threadIdx.x];
    float s = v * v;
#pragma unroll
    for (int off = 16; off > 0; off >>= 1) s += __shfl_xor_sync(~0u, s, off);
    __shared__ float red[8];
    if ((threadIdx.x & 31) == 0) red[threadIdx.x >> 5] = s;
    __syncthreads();
    float tot = red[0] + red[1] + red[2] + red[3] +
                red[4] + red[5] + red[6] + red[7];
    float inv = rsqrtf(tot * (1.0f / DQ) + 1e-5f);
    out[(size_t)t * DQ + threadIdx.x] = v * inv * w[threadIdx.x];
}

// ---------------------------------------------------------------------------
// generic SGEMM: C[M,N] = A[M,K] @ B[N,K]^T (+bias) (+=C if accum)
// ---------------------------------------------------------------------------
__global__ void __launch_bounds__(256) k_gemm(const float* __restrict__ A, int lda,
                                              const float* __restrict__ Bw, int ldb,
                                              float* __restrict__ C, int ldc,
                                              int M, int N, int K,
                                              const float* __restrict__ bias,
                                              int accum) {
    __shared__ float As[16][68];
    __shared__ float Bs[16][68];
    int m0 = blockIdx.y * 64, n0 = blockIdx.x * 64;
    int ty = threadIdx.x >> 4, tx = threadIdx.x & 15;
    float acc[4][4] = {};
    for (int k0 = 0; k0 < K; k0 += 16) {
        for (int i = threadIdx.x; i < 1024; i += 256) {
            int r = i >> 4, kk = i & 15;
            int gk = k0 + kk;
            As[kk][r] = (m0 + r < M && gk < K) ? A[(size_t)(m0 + r) * lda + gk] : 0.f;
            Bs[kk][r] = (n0 + r < N && gk < K) ? Bw[(size_t)(n0 + r) * ldb + gk] : 0.f;
        }
        __syncthreads();
#pragma unroll
        for (int kk = 0; kk < 16; ++kk) {
            float4 av = *reinterpret_cast<const float4*>(&As[kk][ty * 4]);
            float4 bv = *reinterpret_cast<const float4*>(&Bs[kk][tx * 4]);
            float a[4] = {av.x, av.y, av.z, av.w};
            float b[4] = {bv.x, bv.y, bv.z, bv.w};
#pragma unroll
            for (int i = 0; i < 4; ++i)
#pragma unroll
                for (int j = 0; j < 4; ++j) acc[i][j] += a[i] * b[j];
        }
        __syncthreads();
    }
#pragma unroll
    for (int i = 0; i < 4; ++i) {
        int r = m0 + ty * 4 + i;
        if (r >= M) continue;
#pragma unroll
        for (int j = 0; j < 4; ++j) {
            int c = n0 + tx * 4 + j;
            if (c >= N) continue;
            float v = acc[i][j];
            if (bias) v += bias[c];
            if (accum) v += C[(size_t)r * ldc + c];
            C[(size_t)r * ldc + c] = v;
        }
    }
}

// ---------------------------------------------------------------------------
// causal depthwise conv4 + silu
// ---------------------------------------------------------------------------
__global__ void k_convsilu(const float* __restrict__ cw,
                           const float* __restrict__ cb, int T, int Lc) {
    int i = blockIdx.x * 256 + threadIdx.x;
    if (i >= T * EDQ) return;
    int t = i >> 9, e = i & 511;
    int l = t % Lc;
    float acc = cb[e];
#pragma unroll
    for (int k = 0; k < 4; ++k) {
        int li = l + k - 3;
        if (li >= 0) acc += g_xz[(size_t)(t + k - 3) * 1024 + e] * cw[e * 4 + k];
    }
    acc = acc / (1.f + __expf(-acc));
    g_xcs[i] = acc;
}

// ---------------------------------------------------------------------------
// 16-way state-parallel fused scan.
// lane n = lane&15 owns one state; warp covers 2 channels (eh = lane>>4).
// dt-proj + y-output both via 4-step shfl_xor reduce within the 16-lane group.
// grid (32, BQ) x 256 threads -> 2048 warps.
// ---------------------------------------------------------------------------
__global__ void __launch_bounds__(256) k_scan_p(const float* __restrict__ A_log,
                                                const float* __restrict__ Dp,
                                                const float* __restrict__ dt_w,
                                                const float* __restrict__ dt_b,
                                                int Lc) {
    int tid = threadIdx.x;
    int wpb = tid >> 5;               // warp in block (0..7)
    int lane = tid & 31;
    int n  = lane & 15;
    int eh = lane >> 4;
    int e  = blockIdx.x * 16 + wpb * 2 + eh;
    int b  = blockIdx.y;

    float negA  = -__expf(A_log[e * NSTQ + n]);
    float dtw_n = dt_w[e * DTRQ + n];
    float dtb   = dt_b[e];
    float Dv    = Dp[e];
    float h = 0.f;

    for (int t = 0; t < Lc; ++t) {
        size_t idx = (size_t)(b * Lc + t);
        const float* bc = g_dbc + idx * 48;
        float xv = g_xcs[idx * EDQ + e];
        float dtp = __ldg(bc + n) * dtw_n;
        float Bn  = __ldg(bc + 16 + n);
        float Cn  = __ldg(bc + 32 + n);
        dtp += __shfl_xor_sync(0xffffffffu, dtp, 1);
        dtp += __shfl_xor_sync(0xffffffffu, dtp, 2);
        dtp += __shfl_xor_sync(0xffffffffu, dtp, 4);
        dtp += __shfl_xor_sync(0xffffffffu, dtp, 8);
        float draw = dtp + dtb;
        float dlt = (draw > 20.f) ? draw : log1pf(__expf(draw));
        h = __expf(dlt * negA) * h + dlt * xv * Bn;
        float y = h * Cn;
        y += __shfl_xor_sync(0xffffffffu, y, 1);
        y += __shfl_xor_sync(0xffffffffu, y, 2);
        y += __shfl_xor_sync(0xffffffffu, y, 4);
        y += __shfl_xor_sync(0xffffffffu, y, 8);
        if (n == 0) {
            float z = g_xz[idx * 1024 + EDQ + e];
            float sz = z / (1.f + __expf(-z));
            g_ys[idx * EDQ + e] = (y + Dv * xv) * sz;
        }
    }
}

// ---------------------------------------------------------------------------
// whole backward Mamba layer (T=1 per batch): one block per batch element
// ---------------------------------------------------------------------------
__global__ void __launch_bounds__(256) k_bwd_layer(
    const float* __restrict__ norm_w, const float* __restrict__ in_w,
    const float* __restrict__ conv_w, const float* __restrict__ conv_b,
    const float* __restrict__ xp_w,  const float* __restrict__ dt_w,
    const float* __restrict__ dt_b,  const float* __restrict__ Dp,
    const float* __restrict__ out_w) {
    __shared__ float sx[256], sxn[256], sxcs[512], sz[512], sdbc[48], sys[512];
    __shared__ float sred[8];
    __shared__ float sbc;
    int b = blockIdx.x, tid = threadIdx.x;
    int lane = tid & 31, wp = tid >> 5;

    float xv = g_xb[b * DQ + tid];
    sx[tid] = xv;
    float s = xv * xv;
#pragma unroll
    for (int off = 16; off > 0; off >>= 1) s += __shfl_xor_sync(~0u, s, off);
    if (lane == 0) sred[wp] = s;
    __syncthreads();
    float tot = sred[0] + sred[1] + sred[2] + sred[3] +
                sred[4] + sred[5] + sred[6] + sred[7];
    float inv = rsqrtf(tot * (1.0f / DQ) + 1e-5f);
    sxn[tid] = xv * inv * norm_w[tid];
    __syncthreads();

    for (int q = 0; q < 4; ++q) {
        int o = q * 256 + tid;
        float acc = 0.f;
        const float* wr = in_w + (size_t)o * DQ;
        for (int k = 0; k < 256; ++k) acc += sxn[k] * wr[k];
        if (o < EDQ) {
            float v = acc * conv_w[o * 4 + 3] + conv_b[o];
            sxcs[o] = v / (1.f + __expf(-v));
        } else {
            sz[o - EDQ] = acc;
        }
    }
    __syncthreads();

    for (int rr = 0; rr < 6; ++rr) {
        int r = wp * 6 + rr;
        float a = 0.f;
        const float* wr = xp_w + (size_t)r * EDQ;
        for (int k = lane; k < 512; k += 32) a += sxcs[k] * wr[k];
#pragma unroll
        for (int off = 16; off > 0; off >>= 1) a += __shfl_xor_sync(~0u, a, off);
        if (lane == 0) sdbc[r] = a;
    }
    __syncthreads();
    if (tid == 0) {
        float a = 0.f;
#pragma unroll
        for (int n = 0; n < NSTQ; ++n) a += sdbc[16 + n] * sdbc[32 + n];
        sbc = a;
    }
    __syncthreads();

    for (int q = 0; q < 2; ++q) {
        int e = q * 256 + tid;
        float d = dt_b[e];
        const float* wr = dt_w + e * DTRQ;
#pragma unroll
        for (int n = 0; n < DTRQ; ++n) d += sdbc[n] * wr[n];
        d = (d > 20.f) ? d : log1pf(__expf(d));
        float xc_ = sxcs[e];
        float y = d * xc_ * sbc + Dp[e] * xc_;
        float z = sz[e];
        sys[e] = y * (z / (1.f + __expf(-z)));
    }
    __syncthreads();

    float o = sx[tid];
    const float* wr = out_w + (size_t)tid * EDQ;
    for (int k = 0; k < 512; ++k) o += sys[k] * wr[k];
    g_xb[b * DQ + tid] = o;
}

// ---------------------------------------------------------------------------
// head: concat(xc[:, -1], xb) -> fc1 -> fc2
// ---------------------------------------------------------------------------
__global__ void __launch_bounds__(256) k_head(const float* __restrict__ fc_w,
                                              const float* __restrict__ fc_b,
                                              const float* __restrict__ fc2_w,
                                              const float* __restrict__ fc2_b,
                                              float* __restrict__ out) {
    __shared__ float sxl[512], sfc1[256];
    int b = blockIdx.x, tid = threadIdx.x;
    sxl[tid]       = g_xc[(size_t)(b * LQ + LQ - 1) * DQ + tid];
    sxl[256 + tid] = g_xb[b * DQ + tid];
    __syncthreads();
    float a = fc_b[tid];
    const float* wr = fc_w + (size_t)tid * (2 * DQ);
    for (int k = 0; k < 512; ++k) a += sxl[k] * wr[k];
    sfc1[tid] = a;
    __syncthreads();
    if (tid < 2) {
        float o = fc2_b[tid];
        const float* wr2 = fc2_w + tid * DQ;
        for (int k = 0; k < 256; ++k) o += sfc1[k] * wr2[k];
        out[b * 2 + tid] = o;
    }
}

// ---------------------------------------------------------------------------
// Host-side driver
// ---------------------------------------------------------------------------
static float* symf(const void* s) {
    void* p = nullptr;
    cudaGetSymbolAddress(&p, s);
    return (float*)p;
}

static void fwd_layer(float* x, const float* const* p, int l) {
    const float* norm_w = p[0] + (size_t)l * DQ;
    const float* in_w   = p[1] + (size_t)l * 2 * EDQ * DQ;
    const float* conv_w = p[2] + (size_t)l * EDQ * 4;
    const float* conv_b = p[3] + (size_t)l * EDQ;
    const float* xp_w   = p[4] + (size_t)l * (DTRQ + 2 * NSTQ) * EDQ;
    const float* dt_w   = p[5] + (size_t)l * EDQ * DTRQ;
    const float* dt_b   = p[6] + (size_t)l * EDQ;
    const float* A_log  = p[7] + (size_t)l * EDQ * NSTQ;
    const float* Dp     = p[8] + (size_t)l * EDQ;
    const float* out_w  = p[9] + (size_t)l * DQ * EDQ;

    const int T = NIMG;
    float* xn  = symf(g_xn);
    float* xz  = symf(g_xz);
    float* xcs = symf(g_xcs);
    float* dbc = symf(g_dbc);
    float* ys  = symf(g_ys);

    k_rms<<<T, 256>>>(x, norm_w, xn);
    k_gemm<<<dim3(16, 16), 256>>>(xn, DQ, in_w, DQ, xz, 1024, T, 1024, DQ, nullptr, 0);
    k_convsilu<<<(T * EDQ + 255) / 256, 256>>>(conv_w, conv_b, T, LQ);
    k_gemm<<<dim3(1, 16), 256>>>(xcs, EDQ, xp_w, EDQ, dbc, 48, T, 48, EDQ, nullptr, 0);
    k_scan_p<<<dim3(32, BQ), 256>>>(A_log, Dp, dt_w, dt_b, LQ);
    k_gemm<<<dim3(4, 16), 256>>>(ys, EDQ, out_w, EDQ, x, DQ, T, DQ, EDQ, nullptr, 1);
}

extern "C" void kernel_launch(void* const* d_in, const int* in_sizes, int n_in,
                              void* d_out, int out_size) {
    const float* video = (const float*)d_in[0];
    const float* audio = (const float*)d_in[1];
    const float* c1w = (const float*)d_in[2];
    const float* c1b = (const float*)d_in[3];
    const float* c2w = (const float*)d_in[4];
    const float* c2b = (const float*)d_in[5];
    const float* fcw = (const float*)d_in[6];
    const float* fcb = (const float*)d_in[7];
    const float* fwdp[10];
    const float* bwdp[10];
    for (int i = 0; i < 10; ++i) fwdp[i] = (const float*)d_in[8 + i];
    for (int i = 0; i < 10; ++i) bwdp[i] = (const float*)d_in[18 + i];
    const float* fc_w  = (const float*)d_in[28];
    const float* fc_b  = (const float*)d_in[29];
    const float* fc2_w = (const float*)d_in[30];
    const float* fc2_b = (const float*)d_in[31];
    float* out = (float*)d_out;

    cudaFuncSetAttribute(k_conv1_mma, cudaFuncAttributeMaxDynamicSharedMemorySize,
                         C1_SMEM_BYTES);
    cudaFuncSetAttribute(k_conv2_mma, cudaFuncAttributeMaxDynamicSharedMemorySize,
                         C2_SMEM_BYTES);

    // capture slot 4 = k_conv2_mma (measure the fp16 conv2)
    k_audio<<<(BQ * LQ * N_MFCC + 255) / 256, 256>>>(audio);          // 1
    k_conv1_mma<<<NIMG, 512, C1_SMEM_BYTES>>>(video, c1w, c1b);       // 2
    k_filler<<<1, 32>>>();                                            // 3
    k_conv2_mma<<<NIMG, 256, C2_SMEM_BYTES>>>(c2w, c2b);              // 4 (captured)
    k_cnnfc<<<NIMG, 256>>>(fcw, fcb);                                 // 5
    k_lastcol<<<(BQ * DQ + 255) / 256, 256>>>();                      // 6

    float* xc = symf(g_xc);

    for (int l = 0; l < NLQ; ++l) fwd_layer(xc, fwdp, l);

    for (int l = 0; l < NLQ; ++l) {
        const float* p[9];
        p[0] = bwdp[0] + (size_t)l * DQ;
        p[1] = bwdp[1] + (size_t)l * 2 * EDQ * DQ;
        p[2] = bwdp[2] + (size_t)l * EDQ * 4;
        p[3] = bwdp[3] + (size_t)l * EDQ;
        p[4] = bwdp[4] + (size_t)l * (DTRQ + 2 * NSTQ) * EDQ;
        p[5] = bwdp[5] + (size_t)l * EDQ * DTRQ;
        p[6] = bwdp[6] + (size_t)l * EDQ;
        p[7] = bwdp[8] + (size_t)l * EDQ;       // D
        p[8] = bwdp[9] + (size_t)l * DQ * EDQ;  // out_w
        k_bwd_layer<<<BQ, 256>>>(p[0], p[1], p[2], p[3], p[4], p[5], p[6],
                                 p[7], p[8]);
    }

    k_head<<<BQ, 256>>>(fc_w, fc_b, fc2_w, fc2_b, out);
}